// round 10
// baseline (speedup 1.0000x reference)
#include <cuda_runtime.h>
#include <cuda_fp16.h>

#define Dn 24
#define Hn 96
#define Wn 192
#define HWn (Hn * Wn)          // 18432
#define Pn (Dn * HWn)          // 442368

typedef unsigned long long ull;
typedef unsigned int uint;

#define H2_ONES 0x3C003C00u    // half2 {1, 1}

// Scratch (device globals — allocation forbidden)
__device__ float g_q[Pn * 2];      // [p][2], q pre-scaled by log2(e)
__device__ float g_k[Pn * 2];      // [p][2]
__device__ uint  g_vh[Pn * 8];     // [p][8] half2: channels (2j, 2j+1)
__device__ float g_y[Pn * 16];     // intermediate image, [c][p]
__device__ float g_sH[Pn];
__device__ uint  g_oh[Pn * 8];     // unnormalized out_H, half2 channel pairs

// ---- helpers ---------------------------------------------------------------
__device__ __forceinline__ void F2(ull& d, ull a, ull b, ull c) {
    asm("fma.rn.f32x2 %0,%1,%2,%3;" : "=l"(d) : "l"(a), "l"(b), "l"(c));
}
__device__ __forceinline__ ull pack2(float lo, float hi) {
    ull r; asm("mov.b64 %0,{%1,%2};" : "=l"(r) : "f"(lo), "f"(hi)); return r;
}
__device__ __forceinline__ ull dup2(float v) { return pack2(v, v); }
__device__ __forceinline__ float2 unpack2(ull v) {
    float2 r; asm("mov.b64 {%0,%1},%2;" : "=f"(r.x), "=f"(r.y) : "l"(v)); return r;
}
__device__ __forceinline__ uint h2pack(float lo, float hi) {   // {lo, hi}
    uint u; asm("cvt.rn.f16x2.f32 %0,%1,%2;" : "=r"(u) : "f"(hi), "f"(lo)); return u;
}
__device__ __forceinline__ uint ex2h2(uint e) {                // 2 exps, 1 MUFU op
    uint r; asm("ex2.approx.f16x2 %0,%1;" : "=r"(r) : "r"(e)); return r;
}
__device__ __forceinline__ float2 h2unpack(uint u) {
    __half2 h = *reinterpret_cast<__half2*>(&u);
    return __half22float2(h);
}
__device__ __forceinline__ void mmah(float& d0, float& d1, float& d2, float& d3,
                                     uint a0, uint a1, uint b0) {
    asm("mma.sync.aligned.m16n8k8.row.col.f32.f16.f16.f32 "
        "{%0,%1,%2,%3},{%4,%5},{%6},{%0,%1,%2,%3};"
        : "+f"(d0), "+f"(d1), "+f"(d2), "+f"(d3)
        : "r"(a0), "r"(a1), "r"(b0));
}

#define L2E 1.44269504088896340736f

// ---------------------------------------------------------------------------
// QKV projection: 2 pixels/thread; v stored fp16 (half2 channel pairs).
// ---------------------------------------------------------------------------
__global__ __launch_bounds__(128) void qkv_kernel(const float* __restrict__ xin,
                           const float* __restrict__ qw, const float* __restrict__ qb,
                           const float* __restrict__ kw, const float* __restrict__ kb,
                           const float* __restrict__ vw, const float* __restrict__ vb)
{
    __shared__ float s_qw[32], s_kw[32], s_qb[2], s_kb[2];
    __shared__ ull s_vw[16][8];
    __shared__ ull s_vb[8];
    const float* x = xin ? xin : g_y;

    int t = threadIdx.x;
    {
        int c = t & 15, j = t >> 4;
        s_vw[c][j] = pack2(vw[(2 * j) * 16 + c], vw[(2 * j + 1) * 16 + c]);
    }
    if (t < 32)       s_qw[t]      = qw[t];
    else if (t < 64)  s_kw[t - 32] = kw[t - 32];
    else if (t < 66)  s_qb[t - 64] = qb[t - 64];
    else if (t < 68)  s_kb[t - 66] = kb[t - 66];
    else if (t < 76)  s_vb[t - 68] = pack2(vb[2 * (t - 68)], vb[2 * (t - 68) + 1]);
    __syncthreads();

    int p = blockIdx.x * 256 + 2 * t;   // 2 consecutive pixels

    float2 xv[16];
#pragma unroll
    for (int c = 0; c < 16; c++) xv[c] = *(const float2*)&x[c * Pn + p];

    float qa0 = s_qb[0], qa1 = s_qb[1], ka0 = s_kb[0], ka1 = s_kb[1];
    float qb0 = s_qb[0], qb1 = s_qb[1], kb0 = s_kb[0], kb1 = s_kb[1];
#pragma unroll
    for (int c = 0; c < 16; c++) {
        float wq0 = s_qw[c], wq1 = s_qw[16 + c], wk0 = s_kw[c], wk1 = s_kw[16 + c];
        qa0 = fmaf(wq0, xv[c].x, qa0);  qb0 = fmaf(wq0, xv[c].y, qb0);
        qa1 = fmaf(wq1, xv[c].x, qa1);  qb1 = fmaf(wq1, xv[c].y, qb1);
        ka0 = fmaf(wk0, xv[c].x, ka0);  kb0 = fmaf(wk0, xv[c].y, kb0);
        ka1 = fmaf(wk1, xv[c].x, ka1);  kb1 = fmaf(wk1, xv[c].y, kb1);
    }
    *(float4*)&g_q[p * 2] = make_float4(qa0 * L2E, qa1 * L2E, qb0 * L2E, qb1 * L2E);
    *(float4*)&g_k[p * 2] = make_float4(ka0, ka1, kb0, kb1);

    ull ava[8], avb[8];
#pragma unroll
    for (int j = 0; j < 8; j++) { ava[j] = s_vb[j]; avb[j] = s_vb[j]; }
#pragma unroll
    for (int c = 0; c < 16; c++) {
        ull xa = dup2(xv[c].x), xb = dup2(xv[c].y);
#pragma unroll
        for (int j = 0; j < 8; j++) {
            F2(ava[j], s_vw[c][j], xa, ava[j]);
            F2(avb[j], s_vw[c][j], xb, avb[j]);
        }
    }
    uint ha[8], hb[8];
#pragma unroll
    for (int j = 0; j < 8; j++) {
        float2 fa = unpack2(ava[j]), fb = unpack2(avb[j]);
        ha[j] = h2pack(fa.x, fa.y);
        hb[j] = h2pack(fb.x, fb.y);
    }
    uint4* vp = (uint4*)&g_vh[(size_t)p * 8];
    vp[0] = make_uint4(ha[0], ha[1], ha[2], ha[3]);
    vp[1] = make_uint4(ha[4], ha[5], ha[6], ha[7]);
    vp[2] = make_uint4(hb[0], hb[1], hb[2], hb[3]);
    vp[3] = make_uint4(hb[4], hb[5], hb[6], hb[7]);
}

// ---------------------------------------------------------------------------
// Pass A (fp16 MMA): 2 column lines per block, 12 warps (6 per column).
// __launch_bounds__(384, 2): cap regs so 2 blocks/SM are resident.
// ---------------------------------------------------------------------------
__global__ __launch_bounds__(384, 2) void passA_kernel()
{
    __shared__ __align__(16) float2 s_q[2][96], s_k[2][96];
    __shared__ uint sVh[2][48 * 24];   // [col][rowpair*24 + ch]

    int d = blockIdx.y, t = threadIdx.x;
    int w2 = blockIdx.x * 2;

    if (t < 192) {
        int cc = t / 96, row = t % 96;
        int p = d * HWn + row * Wn + w2 + cc;
        s_q[cc][row] = ((const float2*)g_q)[p];
        s_k[cc][row] = ((const float2*)g_k)[p];
    } else {
        int t2 = t - 192;                 // 0..191
        int cc = t2 / 96, rem = t2 % 96;
        int rp = rem >> 1, hs = rem & 1;
        int pe = d * HWn + (2 * rp) * Wn + w2 + cc;
        int po = pe + Wn;
        uint4 e = *(const uint4*)&g_vh[(size_t)pe * 8 + hs * 4];
        uint4 o = *(const uint4*)&g_vh[(size_t)po * 8 + hs * 4];
        uint* dst = &sVh[cc][rp * 24 + hs * 8];
        dst[0] = __byte_perm(e.x, o.x, 0x5410); dst[1] = __byte_perm(e.x, o.x, 0x7632);
        dst[2] = __byte_perm(e.y, o.y, 0x5410); dst[3] = __byte_perm(e.y, o.y, 0x7632);
        dst[4] = __byte_perm(e.z, o.z, 0x5410); dst[5] = __byte_perm(e.z, o.z, 0x7632);
        dst[6] = __byte_perm(e.w, o.w, 0x5410); dst[7] = __byte_perm(e.w, o.w, 0x7632);
    }
    __syncthreads();

    int warp = t >> 5, lane = t & 31, g = lane >> 2, tig = lane & 3;
    int col = warp / 6, warpIn = warp % 6;
    int lineBase = d * HWn + w2 + col;
    int r0 = warpIn * 16 + g, r1 = r0 + 8;
    float2 q0 = s_q[col][r0], q1 = s_q[col][r1];

    float D0[4] = {0, 0, 0, 0};
    float D1[4] = {0, 0, 0, 0};
    float S[4]  = {0, 0, 0, 0};

#pragma unroll 2
    for (int kt = 0; kt < 12; kt++) {
        int c0 = kt * 8 + 2 * tig;
        float4 kk = *(const float4*)&s_k[col][c0];   // k[c0], k[c0+1]
        float e00 = fmaf(q0.y, kk.y, q0.x * kk.x);
        float e01 = fmaf(q0.y, kk.w, q0.x * kk.z);
        float e10 = fmaf(q1.y, kk.y, q1.x * kk.x);
        float e11 = fmaf(q1.y, kk.w, q1.x * kk.z);
        if (c0 == r0)     e00 = -1e4f;
        if (c0 + 1 == r0) e01 = -1e4f;
        if (c0 == r1)     e10 = -1e4f;
        if (c0 + 1 == r1) e11 = -1e4f;
        uint a0 = ex2h2(h2pack(e00, e01));
        uint a1 = ex2h2(h2pack(e10, e11));
        int rp = kt * 4 + tig;
        uint b0 = sVh[col][rp * 24 + g];
        uint b1 = sVh[col][rp * 24 + 8 + g];
        mmah(D0[0], D0[1], D0[2], D0[3], a0, a1, b0);
        mmah(D1[0], D1[1], D1[2], D1[3], a0, a1, b1);
        mmah(S[0],  S[1],  S[2],  S[3],  a0, a1, H2_ONES);
    }

    int p0 = lineBase + r0 * Wn, p1 = lineBase + r1 * Wn;
    if (tig == 0) { g_sH[p0] = S[0]; g_sH[p1] = S[2]; }
    g_oh[(size_t)p0 * 8 + tig]     = h2pack(D0[0], D0[1]);
    g_oh[(size_t)p1 * 8 + tig]     = h2pack(D0[2], D0[3]);
    g_oh[(size_t)p0 * 8 + 4 + tig] = h2pack(D1[0], D1[1]);
    g_oh[(size_t)p1 * 8 + 4 + tig] = h2pack(D1[2], D1[3]);
}

// ---------------------------------------------------------------------------
// Pass B (fp16 MMA): one row line per block, 12 warps. Combine + residual.
// __launch_bounds__(384, 2); sH/oh prefetched before the mainloop.
// ---------------------------------------------------------------------------
__global__ __launch_bounds__(384, 2) void passB_kernel(const float* __restrict__ xin,
                                                       float* __restrict__ dst,
                                                       const float* __restrict__ gammap)
{
    __shared__ __align__(16) float2 s_q[192], s_k[192];
    __shared__ uint sVh[96 * 24];

    int d = blockIdx.y, h = blockIdx.x, t = threadIdx.x;
    int lineBase = d * HWn + h * Wn;
    const float* x = xin ? xin : g_y;
    float*       y = dst ? dst : g_y;

    if (t < 192) {
        int p = lineBase + t;
        s_q[t] = ((const float2*)g_q)[p];
        s_k[t] = ((const float2*)g_k)[p];
    } else {
        int t2 = t - 192;                 // 0..191
        int rp = t2 >> 1, hs = t2 & 1;
        int pe = lineBase + 2 * rp;
        uint4 e = *(const uint4*)&g_vh[(size_t)pe * 8 + hs * 4];
        uint4 o = *(const uint4*)&g_vh[(size_t)(pe + 1) * 8 + hs * 4];
        uint* dstp = &sVh[rp * 24 + hs * 8];
        dstp[0] = __byte_perm(e.x, o.x, 0x5410); dstp[1] = __byte_perm(e.x, o.x, 0x7632);
        dstp[2] = __byte_perm(e.y, o.y, 0x5410); dstp[3] = __byte_perm(e.y, o.y, 0x7632);
        dstp[4] = __byte_perm(e.z, o.z, 0x5410); dstp[5] = __byte_perm(e.z, o.z, 0x7632);
        dstp[6] = __byte_perm(e.w, o.w, 0x5410); dstp[7] = __byte_perm(e.w, o.w, 0x7632);
    }

    int warp = t >> 5, lane = t & 31, g = lane >> 2, tig = lane & 3;
    int r0 = warp * 16 + g, r1 = r0 + 8;
    int p0 = lineBase + r0, p1 = lineBase + r1;

    // ---- prefetch epilogue operands: overlap their latency with the mainloop
    float sH0 = g_sH[p0], sH1 = g_sH[p1];
    uint oh00 = g_oh[(size_t)p0 * 8 + tig];
    uint oh01 = g_oh[(size_t)p0 * 8 + 4 + tig];
    uint oh10 = g_oh[(size_t)p1 * 8 + tig];
    uint oh11 = g_oh[(size_t)p1 * 8 + 4 + tig];
    float gamma = gammap[0];

    __syncthreads();

    float2 q0 = s_q[r0], q1 = s_q[r1];

    float D0[4] = {0, 0, 0, 0};
    float D1[4] = {0, 0, 0, 0};
    float S[4]  = {0, 0, 0, 0};

#pragma unroll 2
    for (int kt = 0; kt < 24; kt++) {
        int c0 = kt * 8 + 2 * tig;
        float4 kk = *(const float4*)&s_k[c0];
        float e00 = fmaf(q0.y, kk.y, q0.x * kk.x);
        float e01 = fmaf(q0.y, kk.w, q0.x * kk.z);
        float e10 = fmaf(q1.y, kk.y, q1.x * kk.x);
        float e11 = fmaf(q1.y, kk.w, q1.x * kk.z);
        uint a0 = ex2h2(h2pack(e00, e01));
        uint a1 = ex2h2(h2pack(e10, e11));
        int rp = kt * 4 + tig;
        uint b0 = sVh[rp * 24 + g];
        uint b1 = sVh[rp * 24 + 8 + g];
        mmah(D0[0], D0[1], D0[2], D0[3], a0, a1, b0);
        mmah(D1[0], D1[1], D1[2], D1[3], a0, a1, b1);
        mmah(S[0],  S[1],  S[2],  S[3],  a0, a1, H2_ONES);
    }

    float inv0 = __fdividef(gamma, S[0] + sH0);
    float inv1 = __fdividef(gamma, S[2] + sH1);

    {
        float2 oh0 = h2unpack(oh00);
        float2 oh1 = h2unpack(oh10);
        int c = 2 * tig;
        y[c * Pn + p0]       = x[c * Pn + p0]       + (D0[0] + oh0.x) * inv0;
        y[(c + 1) * Pn + p0] = x[(c + 1) * Pn + p0] + (D0[1] + oh0.y) * inv0;
        y[c * Pn + p1]       = x[c * Pn + p1]       + (D0[2] + oh1.x) * inv1;
        y[(c + 1) * Pn + p1] = x[(c + 1) * Pn + p1] + (D0[3] + oh1.y) * inv1;
    }
    {
        float2 oh0 = h2unpack(oh01);
        float2 oh1 = h2unpack(oh11);
        int c = 8 + 2 * tig;
        y[c * Pn + p0]       = x[c * Pn + p0]       + (D1[0] + oh0.x) * inv0;
        y[(c + 1) * Pn + p0] = x[(c + 1) * Pn + p0] + (D1[1] + oh0.y) * inv0;
        y[c * Pn + p1]       = x[c * Pn + p1]       + (D1[2] + oh1.x) * inv1;
        y[(c + 1) * Pn + p1] = x[(c + 1) * Pn + p1] + (D1[3] + oh1.y) * inv1;
    }
}

// ---------------------------------------------------------------------------
extern "C" void kernel_launch(void* const* d_in, const int* in_sizes, int n_in,
                              void* d_out, int out_size)
{
    const float* x     = (const float*)d_in[0];
    const float* qw    = (const float*)d_in[1];
    const float* qb    = (const float*)d_in[2];
    const float* kw    = (const float*)d_in[3];
    const float* kb    = (const float*)d_in[4];
    const float* vw    = (const float*)d_in[5];
    const float* vb    = (const float*)d_in[6];
    const float* gamma = (const float*)d_in[7];
    float* out = (float*)d_out;

    dim3 gA(Wn / 2, Dn);   // 96 x 24 blocks, 384 threads
    dim3 gB(Hn, Dn);       // 96 x 24 blocks, 384 threads
    int qkvBlocks = Pn / 256;

    qkv_kernel<<<qkvBlocks, 128>>>(x, qw, qb, kw, kb, vw, vb);
    passA_kernel<<<gA, 384>>>();
    passB_kernel<<<gB, 384>>>(x, nullptr, gamma);

    qkv_kernel<<<qkvBlocks, 128>>>(nullptr, qw, qb, kw, kb, vw, vb);
    passA_kernel<<<gA, 384>>>();
    passB_kernel<<<gB, 384>>>(nullptr, out, gamma);
}

// round 11
// speedup vs baseline: 1.1353x; 1.1353x over previous
#include <cuda_runtime.h>
#include <cuda_fp16.h>

#define Dn 24
#define Hn 96
#define Wn 192
#define HWn (Hn * Wn)          // 18432
#define Pn (Dn * HWn)          // 442368

typedef unsigned long long ull;
typedef unsigned int uint;

#define H2_ONES 0x3C003C00u    // half2 {1, 1}

// Scratch (device globals — allocation forbidden)
__device__ float g_q[Pn * 2];      // [p][2], q pre-scaled by log2(e)
__device__ float g_k[Pn * 2];      // [p][2]
__device__ uint  g_vh[Pn * 8];     // [p][8] half2: channels (2j, 2j+1)
__device__ float g_y[Pn * 16];     // intermediate image, [c][p]
__device__ float g_sH[Pn];
__device__ uint  g_oh[Pn * 8];     // unnormalized out_H, half2 channel pairs

// ---- helpers ---------------------------------------------------------------
__device__ __forceinline__ void F2(ull& d, ull a, ull b, ull c) {
    asm("fma.rn.f32x2 %0,%1,%2,%3;" : "=l"(d) : "l"(a), "l"(b), "l"(c));
}
__device__ __forceinline__ ull pack2(float lo, float hi) {
    ull r; asm("mov.b64 %0,{%1,%2};" : "=l"(r) : "f"(lo), "f"(hi)); return r;
}
__device__ __forceinline__ ull dup2(float v) { return pack2(v, v); }
__device__ __forceinline__ float2 unpack2(ull v) {
    float2 r; asm("mov.b64 {%0,%1},%2;" : "=f"(r.x), "=f"(r.y) : "l"(v)); return r;
}
__device__ __forceinline__ uint h2pack(float lo, float hi) {   // {lo, hi}
    uint u; asm("cvt.rn.f16x2.f32 %0,%1,%2;" : "=r"(u) : "f"(hi), "f"(lo)); return u;
}
__device__ __forceinline__ uint ex2h2(uint e) {                // 2 exps, 1 MUFU op
    uint r; asm("ex2.approx.f16x2 %0,%1;" : "=r"(r) : "r"(e)); return r;
}
__device__ __forceinline__ uint hmul2(uint a, uint b) {
    uint d; asm("mul.f16x2 %0,%1,%2;" : "=r"(d) : "r"(a), "r"(b)); return d;
}
__device__ __forceinline__ uint hfma2(uint a, uint b, uint c) {
    uint d; asm("fma.rn.f16x2 %0,%1,%2,%3;" : "=r"(d) : "r"(a), "r"(b), "r"(c)); return d;
}
__device__ __forceinline__ float2 h2unpack(uint u) {
    __half2 h = *reinterpret_cast<__half2*>(&u);
    return __half22float2(h);
}
__device__ __forceinline__ void mmah16(float& d0, float& d1, float& d2, float& d3,
                                       uint a0, uint a1, uint a2, uint a3,
                                       uint b0, uint b1) {
    asm("mma.sync.aligned.m16n8k16.row.col.f32.f16.f16.f32 "
        "{%0,%1,%2,%3},{%4,%5,%6,%7},{%8,%9},{%0,%1,%2,%3};"
        : "+f"(d0), "+f"(d1), "+f"(d2), "+f"(d3)
        : "r"(a0), "r"(a1), "r"(a2), "r"(a3), "r"(b0), "r"(b1));
}

#define L2E 1.44269504088896340736f

// ---------------------------------------------------------------------------
// QKV projection: 2 pixels/thread; v stored fp16. q carries the L2E factor.
// ---------------------------------------------------------------------------
__global__ __launch_bounds__(128) void qkv_kernel(const float* __restrict__ xin,
                           const float* __restrict__ qw, const float* __restrict__ qb,
                           const float* __restrict__ kw, const float* __restrict__ kb,
                           const float* __restrict__ vw, const float* __restrict__ vb)
{
    __shared__ float s_qw[32], s_kw[32], s_qb[2], s_kb[2];
    __shared__ ull s_vw[16][8];
    __shared__ ull s_vb[8];
    const float* x = xin ? xin : g_y;

    int t = threadIdx.x;
    {
        int c = t & 15, j = t >> 4;
        s_vw[c][j] = pack2(vw[(2 * j) * 16 + c], vw[(2 * j + 1) * 16 + c]);
    }
    if (t < 32)       s_qw[t]      = qw[t];
    else if (t < 64)  s_kw[t - 32] = kw[t - 32];
    else if (t < 66)  s_qb[t - 64] = qb[t - 64];
    else if (t < 68)  s_kb[t - 66] = kb[t - 66];
    else if (t < 76)  s_vb[t - 68] = pack2(vb[2 * (t - 68)], vb[2 * (t - 68) + 1]);
    __syncthreads();

    int p = blockIdx.x * 256 + 2 * t;   // 2 consecutive pixels

    float2 xv[16];
#pragma unroll
    for (int c = 0; c < 16; c++) xv[c] = *(const float2*)&x[c * Pn + p];

    float qa0 = s_qb[0], qa1 = s_qb[1], ka0 = s_kb[0], ka1 = s_kb[1];
    float qb0 = s_qb[0], qb1 = s_qb[1], kb0 = s_kb[0], kb1 = s_kb[1];
#pragma unroll
    for (int c = 0; c < 16; c++) {
        float wq0 = s_qw[c], wq1 = s_qw[16 + c], wk0 = s_kw[c], wk1 = s_kw[16 + c];
        qa0 = fmaf(wq0, xv[c].x, qa0);  qb0 = fmaf(wq0, xv[c].y, qb0);
        qa1 = fmaf(wq1, xv[c].x, qa1);  qb1 = fmaf(wq1, xv[c].y, qb1);
        ka0 = fmaf(wk0, xv[c].x, ka0);  kb0 = fmaf(wk0, xv[c].y, kb0);
        ka1 = fmaf(wk1, xv[c].x, ka1);  kb1 = fmaf(wk1, xv[c].y, kb1);
    }
    *(float4*)&g_q[p * 2] = make_float4(qa0 * L2E, qa1 * L2E, qb0 * L2E, qb1 * L2E);
    *(float4*)&g_k[p * 2] = make_float4(ka0, ka1, kb0, kb1);

    ull ava[8], avb[8];
#pragma unroll
    for (int j = 0; j < 8; j++) { ava[j] = s_vb[j]; avb[j] = s_vb[j]; }
#pragma unroll
    for (int c = 0; c < 16; c++) {
        ull xa = dup2(xv[c].x), xb = dup2(xv[c].y);
#pragma unroll
        for (int j = 0; j < 8; j++) {
            F2(ava[j], s_vw[c][j], xa, ava[j]);
            F2(avb[j], s_vw[c][j], xb, avb[j]);
        }
    }
    uint ha[8], hb[8];
#pragma unroll
    for (int j = 0; j < 8; j++) {
        float2 fa = unpack2(ava[j]), fb = unpack2(avb[j]);
        ha[j] = h2pack(fa.x, fa.y);
        hb[j] = h2pack(fb.x, fb.y);
    }
    uint4* vp = (uint4*)&g_vh[(size_t)p * 8];
    vp[0] = make_uint4(ha[0], ha[1], ha[2], ha[3]);
    vp[1] = make_uint4(ha[4], ha[5], ha[6], ha[7]);
    vp[2] = make_uint4(hb[0], hb[1], hb[2], hb[3]);
    vp[3] = make_uint4(hb[4], hb[5], hb[6], hb[7]);
}

// ---------------------------------------------------------------------------
// Pass A (fp16 MMA k16): 2 column lines per block, 12 warps (6 per column).
// fp16 energies (HMUL2/HFMA2) -> ex2.f16x2 -> A fragments; diag mask on bits.
// ---------------------------------------------------------------------------
__global__ __launch_bounds__(384) void passA_kernel()
{
    __shared__ uint s_qh[2][96];                       // {qx,qy} half2 per row
    __shared__ __align__(4) __half s_kxh[2][96], s_kyh[2][96];
    __shared__ uint sVh[2][48 * 24];                   // [col][rowpair*24 + ch]

    int d = blockIdx.y, t = threadIdx.x;
    int w2 = blockIdx.x * 2;

    if (t < 192) {
        int cc = t / 96, row = t % 96;
        int p = d * HWn + row * Wn + w2 + cc;
        float2 q = ((const float2*)g_q)[p];
        float2 k = ((const float2*)g_k)[p];
        s_qh[cc][row] = h2pack(q.x, q.y);
        s_kxh[cc][row] = __float2half(k.x);
        s_kyh[cc][row] = __float2half(k.y);
    } else {
        int t2 = t - 192;                 // 0..191
        int cc = t2 / 96, rem = t2 % 96;
        int rp = rem >> 1, hs = rem & 1;
        int pe = d * HWn + (2 * rp) * Wn + w2 + cc;
        int po = pe + Wn;
        uint4 e = *(const uint4*)&g_vh[(size_t)pe * 8 + hs * 4];
        uint4 o = *(const uint4*)&g_vh[(size_t)po * 8 + hs * 4];
        uint* dst = &sVh[cc][rp * 24 + hs * 8];
        dst[0] = __byte_perm(e.x, o.x, 0x5410); dst[1] = __byte_perm(e.x, o.x, 0x7632);
        dst[2] = __byte_perm(e.y, o.y, 0x5410); dst[3] = __byte_perm(e.y, o.y, 0x7632);
        dst[4] = __byte_perm(e.z, o.z, 0x5410); dst[5] = __byte_perm(e.z, o.z, 0x7632);
        dst[6] = __byte_perm(e.w, o.w, 0x5410); dst[7] = __byte_perm(e.w, o.w, 0x7632);
    }
    __syncthreads();

    int warp = t >> 5, lane = t & 31, g = lane >> 2, tig = lane & 3;
    int col = warp / 6, warpIn = warp % 6;
    int lineBase = d * HWn + w2 + col;
    int r0 = warpIn * 16 + g, r1 = r0 + 8;

    uint qh0 = s_qh[col][r0], qh1 = s_qh[col][r1];
    uint qx0 = __byte_perm(qh0, qh0, 0x1010), qy0 = __byte_perm(qh0, qh0, 0x3232);
    uint qx1 = __byte_perm(qh1, qh1, 0x1010), qy1 = __byte_perm(qh1, qh1, 0x3232);

    float D0[4] = {0, 0, 0, 0};
    float D1[4] = {0, 0, 0, 0};
    float S[4]  = {0, 0, 0, 0};

#pragma unroll
    for (int kt = 0; kt < 6; kt++) {      // 16 keys per iteration
        int pi = kt * 8 + tig;            // key-pair index (cols 2pi, 2pi+1)
        uint kxA = *(const uint*)&s_kxh[col][2 * pi];
        uint kyA = *(const uint*)&s_kyh[col][2 * pi];
        uint kxB = *(const uint*)&s_kxh[col][2 * (pi + 4)];
        uint kyB = *(const uint*)&s_kyh[col][2 * (pi + 4)];

        uint a0 = ex2h2(hfma2(qx0, kxA, hmul2(qy0, kyA)));
        uint a1 = ex2h2(hfma2(qx1, kxA, hmul2(qy1, kyA)));
        uint a2 = ex2h2(hfma2(qx0, kxB, hmul2(qy0, kyB)));
        uint a3 = ex2h2(hfma2(qx1, kxB, hmul2(qy1, kyB)));

        int j0 = 2 * pi, j1 = 2 * (pi + 4);
        if (r0 == j0)     a0 &= 0xFFFF0000u;
        if (r0 == j0 + 1) a0 &= 0x0000FFFFu;
        if (r1 == j0)     a1 &= 0xFFFF0000u;
        if (r1 == j0 + 1) a1 &= 0x0000FFFFu;
        if (r0 == j1)     a2 &= 0xFFFF0000u;
        if (r0 == j1 + 1) a2 &= 0x0000FFFFu;
        if (r1 == j1)     a3 &= 0xFFFF0000u;
        if (r1 == j1 + 1) a3 &= 0x0000FFFFu;

        uint b0lo = sVh[col][pi * 24 + g];
        uint b1lo = sVh[col][(pi + 4) * 24 + g];
        uint b0hi = sVh[col][pi * 24 + 8 + g];
        uint b1hi = sVh[col][(pi + 4) * 24 + 8 + g];

        mmah16(D0[0], D0[1], D0[2], D0[3], a0, a1, a2, a3, b0lo, b1lo);
        mmah16(D1[0], D1[1], D1[2], D1[3], a0, a1, a2, a3, b0hi, b1hi);
        mmah16(S[0],  S[1],  S[2],  S[3],  a0, a1, a2, a3, H2_ONES, H2_ONES);
    }

    int p0 = lineBase + r0 * Wn, p1 = lineBase + r1 * Wn;
    if (tig == 0) { g_sH[p0] = S[0]; g_sH[p1] = S[2]; }
    g_oh[(size_t)p0 * 8 + tig]     = h2pack(D0[0], D0[1]);
    g_oh[(size_t)p1 * 8 + tig]     = h2pack(D0[2], D0[3]);
    g_oh[(size_t)p0 * 8 + 4 + tig] = h2pack(D1[0], D1[1]);
    g_oh[(size_t)p1 * 8 + 4 + tig] = h2pack(D1[2], D1[3]);
}

// ---------------------------------------------------------------------------
// Pass B (fp16 MMA k16): one row line per block, 12 warps. Combine + residual.
// ---------------------------------------------------------------------------
__global__ __launch_bounds__(384) void passB_kernel(const float* __restrict__ xin,
                                                    float* __restrict__ dst,
                                                    const float* __restrict__ gammap)
{
    __shared__ uint s_qh[192];
    __shared__ __align__(4) __half s_kxh[192], s_kyh[192];
    __shared__ uint sVh[96 * 24];

    int d = blockIdx.y, h = blockIdx.x, t = threadIdx.x;
    int lineBase = d * HWn + h * Wn;
    const float* x = xin ? xin : g_y;
    float*       y = dst ? dst : g_y;

    if (t < 192) {
        int p = lineBase + t;
        float2 q = ((const float2*)g_q)[p];
        float2 k = ((const float2*)g_k)[p];
        s_qh[t] = h2pack(q.x, q.y);
        s_kxh[t] = __float2half(k.x);
        s_kyh[t] = __float2half(k.y);
    } else {
        int t2 = t - 192;                 // 0..191
        int rp = t2 >> 1, hs = t2 & 1;
        int pe = lineBase + 2 * rp;
        uint4 e = *(const uint4*)&g_vh[(size_t)pe * 8 + hs * 4];
        uint4 o = *(const uint4*)&g_vh[(size_t)(pe + 1) * 8 + hs * 4];
        uint* dstp = &sVh[rp * 24 + hs * 8];
        dstp[0] = __byte_perm(e.x, o.x, 0x5410); dstp[1] = __byte_perm(e.x, o.x, 0x7632);
        dstp[2] = __byte_perm(e.y, o.y, 0x5410); dstp[3] = __byte_perm(e.y, o.y, 0x7632);
        dstp[4] = __byte_perm(e.z, o.z, 0x5410); dstp[5] = __byte_perm(e.z, o.z, 0x7632);
        dstp[6] = __byte_perm(e.w, o.w, 0x5410); dstp[7] = __byte_perm(e.w, o.w, 0x7632);
    }

    int warp = t >> 5, lane = t & 31, g = lane >> 2, tig = lane & 3;
    int r0 = warp * 16 + g, r1 = r0 + 8;
    int p0 = lineBase + r0, p1 = lineBase + r1;

    float sH0 = g_sH[p0], sH1 = g_sH[p1];
    uint oh00 = g_oh[(size_t)p0 * 8 + tig];
    uint oh01 = g_oh[(size_t)p0 * 8 + 4 + tig];
    uint oh10 = g_oh[(size_t)p1 * 8 + tig];
    uint oh11 = g_oh[(size_t)p1 * 8 + 4 + tig];
    float gamma = gammap[0];

    __syncthreads();

    uint qh0 = s_qh[r0], qh1 = s_qh[r1];
    uint qx0 = __byte_perm(qh0, qh0, 0x1010), qy0 = __byte_perm(qh0, qh0, 0x3232);
    uint qx1 = __byte_perm(qh1, qh1, 0x1010), qy1 = __byte_perm(qh1, qh1, 0x3232);

    float D0[4] = {0, 0, 0, 0};
    float D1[4] = {0, 0, 0, 0};
    float S[4]  = {0, 0, 0, 0};

#pragma unroll 3
    for (int kt = 0; kt < 12; kt++) {
        int pi = kt * 8 + tig;
        uint kxA = *(const uint*)&s_kxh[2 * pi];
        uint kyA = *(const uint*)&s_kyh[2 * pi];
        uint kxB = *(const uint*)&s_kxh[2 * (pi + 4)];
        uint kyB = *(const uint*)&s_kyh[2 * (pi + 4)];

        uint a0 = ex2h2(hfma2(qx0, kxA, hmul2(qy0, kyA)));
        uint a1 = ex2h2(hfma2(qx1, kxA, hmul2(qy1, kyA)));
        uint a2 = ex2h2(hfma2(qx0, kxB, hmul2(qy0, kyB)));
        uint a3 = ex2h2(hfma2(qx1, kxB, hmul2(qy1, kyB)));

        uint b0lo = sVh[pi * 24 + g];
        uint b1lo = sVh[(pi + 4) * 24 + g];
        uint b0hi = sVh[pi * 24 + 8 + g];
        uint b1hi = sVh[(pi + 4) * 24 + 8 + g];

        mmah16(D0[0], D0[1], D0[2], D0[3], a0, a1, a2, a3, b0lo, b1lo);
        mmah16(D1[0], D1[1], D1[2], D1[3], a0, a1, a2, a3, b0hi, b1hi);
        mmah16(S[0],  S[1],  S[2],  S[3],  a0, a1, a2, a3, H2_ONES, H2_ONES);
    }

    float inv0 = __fdividef(gamma, S[0] + sH0);
    float inv1 = __fdividef(gamma, S[2] + sH1);

    {
        float2 oh0 = h2unpack(oh00);
        float2 oh1 = h2unpack(oh10);
        int c = 2 * tig;
        y[c * Pn + p0]       = x[c * Pn + p0]       + (D0[0] + oh0.x) * inv0;
        y[(c + 1) * Pn + p0] = x[(c + 1) * Pn + p0] + (D0[1] + oh0.y) * inv0;
        y[c * Pn + p1]       = x[c * Pn + p1]       + (D0[2] + oh1.x) * inv1;
        y[(c + 1) * Pn + p1] = x[(c + 1) * Pn + p1] + (D0[3] + oh1.y) * inv1;
    }
    {
        float2 oh0 = h2unpack(oh01);
        float2 oh1 = h2unpack(oh11);
        int c = 8 + 2 * tig;
        y[c * Pn + p0]       = x[c * Pn + p0]       + (D1[0] + oh0.x) * inv0;
        y[(c + 1) * Pn + p0] = x[(c + 1) * Pn + p0] + (D1[1] + oh0.y) * inv0;
        y[c * Pn + p1]       = x[c * Pn + p1]       + (D1[2] + oh1.x) * inv1;
        y[(c + 1) * Pn + p1] = x[(c + 1) * Pn + p1] + (D1[3] + oh1.y) * inv1;
    }
}

// ---------------------------------------------------------------------------
extern "C" void kernel_launch(void* const* d_in, const int* in_sizes, int n_in,
                              void* d_out, int out_size)
{
    const float* x     = (const float*)d_in[0];
    const float* qw    = (const float*)d_in[1];
    const float* qb    = (const float*)d_in[2];
    const float* kw    = (const float*)d_in[3];
    const float* kb    = (const float*)d_in[4];
    const float* vw    = (const float*)d_in[5];
    const float* vb    = (const float*)d_in[6];
    const float* gamma = (const float*)d_in[7];
    float* out = (float*)d_out;

    dim3 gA(Wn / 2, Dn);   // 96 x 24 blocks, 384 threads
    dim3 gB(Hn, Dn);       // 96 x 24 blocks, 384 threads
    int qkvBlocks = Pn / 256;

    qkv_kernel<<<qkvBlocks, 128>>>(x, qw, qb, kw, kb, vw, vb);
    passA_kernel<<<gA, 384>>>();
    passB_kernel<<<gB, 384>>>(x, nullptr, gamma);

    qkv_kernel<<<qkvBlocks, 128>>>(nullptr, qw, qb, kw, kb, vw, vb);
    passA_kernel<<<gA, 384>>>();
    passB_kernel<<<gB, 384>>>(nullptr, out, gamma);
}

// round 12
// speedup vs baseline: 1.1553x; 1.0176x over previous
#include <cuda_runtime.h>
#include <cuda_fp16.h>

#define Dn 24
#define Hn 96
#define Wn 192
#define HWn (Hn * Wn)          // 18432
#define Pn (Dn * HWn)          // 442368

typedef unsigned long long ull;
typedef unsigned int uint;

#define H2_ONES 0x3C003C00u    // half2 {1, 1}
#define SVS 40                 // sVh rowpair stride (uints)

// Scratch (device globals — allocation forbidden)
__device__ uint  g_qh[Pn];         // half2 {qx,qy}, q pre-scaled by log2(e)
__device__ uint  g_kh[Pn];         // half2 {kx,ky}
__device__ uint  g_vh[Pn * 8];     // [p][8] half2: channels (2j, 2j+1)
__device__ float g_y[Pn * 16];     // intermediate image, [c][p]
__device__ float g_sH[Pn];
__device__ uint  g_oh[Pn * 8];     // unnormalized out_H, half2 channel pairs

// ---- helpers ---------------------------------------------------------------
__device__ __forceinline__ void F2(ull& d, ull a, ull b, ull c) {
    asm("fma.rn.f32x2 %0,%1,%2,%3;" : "=l"(d) : "l"(a), "l"(b), "l"(c));
}
__device__ __forceinline__ ull pack2(float lo, float hi) {
    ull r; asm("mov.b64 %0,{%1,%2};" : "=l"(r) : "f"(lo), "f"(hi)); return r;
}
__device__ __forceinline__ ull dup2(float v) { return pack2(v, v); }
__device__ __forceinline__ float2 unpack2(ull v) {
    float2 r; asm("mov.b64 {%0,%1},%2;" : "=f"(r.x), "=f"(r.y) : "l"(v)); return r;
}
__device__ __forceinline__ uint h2pack(float lo, float hi) {   // {lo, hi}
    uint u; asm("cvt.rn.f16x2.f32 %0,%1,%2;" : "=r"(u) : "f"(hi), "f"(lo)); return u;
}
__device__ __forceinline__ uint ex2h2(uint e) {                // 2 exps, 1 MUFU op
    uint r; asm("ex2.approx.f16x2 %0,%1;" : "=r"(r) : "r"(e)); return r;
}
__device__ __forceinline__ uint hmul2(uint a, uint b) {
    uint d; asm("mul.f16x2 %0,%1,%2;" : "=r"(d) : "r"(a), "r"(b)); return d;
}
__device__ __forceinline__ uint hfma2(uint a, uint b, uint c) {
    uint d; asm("fma.rn.f16x2 %0,%1,%2,%3;" : "=r"(d) : "r"(a), "r"(b), "r"(c)); return d;
}
__device__ __forceinline__ float2 h2unpack(uint u) {
    __half2 h = *reinterpret_cast<__half2*>(&u);
    return __half22float2(h);
}
__device__ __forceinline__ void mmah16(float& d0, float& d1, float& d2, float& d3,
                                       uint a0, uint a1, uint a2, uint a3,
                                       uint b0, uint b1) {
    asm("mma.sync.aligned.m16n8k16.row.col.f32.f16.f16.f32 "
        "{%0,%1,%2,%3},{%4,%5,%6,%7},{%8,%9},{%0,%1,%2,%3};"
        : "+f"(d0), "+f"(d1), "+f"(d2), "+f"(d3)
        : "r"(a0), "r"(a1), "r"(a2), "r"(a3), "r"(b0), "r"(b1));
}

#define L2E 1.44269504088896340736f

// ---------------------------------------------------------------------------
// QKV projection: 2 pixels/thread; q,k,v all stored fp16.
// ---------------------------------------------------------------------------
__global__ __launch_bounds__(128) void qkv_kernel(const float* __restrict__ xin,
                           const float* __restrict__ qw, const float* __restrict__ qb,
                           const float* __restrict__ kw, const float* __restrict__ kb,
                           const float* __restrict__ vw, const float* __restrict__ vb)
{
    __shared__ float s_qw[32], s_kw[32], s_qb[2], s_kb[2];
    __shared__ ull s_vw[16][8];
    __shared__ ull s_vb[8];
    const float* x = xin ? xin : g_y;

    int t = threadIdx.x;
    {
        int c = t & 15, j = t >> 4;
        s_vw[c][j] = pack2(vw[(2 * j) * 16 + c], vw[(2 * j + 1) * 16 + c]);
    }
    if (t < 32)       s_qw[t]      = qw[t];
    else if (t < 64)  s_kw[t - 32] = kw[t - 32];
    else if (t < 66)  s_qb[t - 64] = qb[t - 64];
    else if (t < 68)  s_kb[t - 66] = kb[t - 66];
    else if (t < 76)  s_vb[t - 68] = pack2(vb[2 * (t - 68)], vb[2 * (t - 68) + 1]);
    __syncthreads();

    int p = blockIdx.x * 256 + 2 * t;   // 2 consecutive pixels

    float2 xv[16];
#pragma unroll
    for (int c = 0; c < 16; c++) xv[c] = *(const float2*)&x[c * Pn + p];

    float qa0 = s_qb[0], qa1 = s_qb[1], ka0 = s_kb[0], ka1 = s_kb[1];
    float qb0 = s_qb[0], qb1 = s_qb[1], kb0 = s_kb[0], kb1 = s_kb[1];
#pragma unroll
    for (int c = 0; c < 16; c++) {
        float wq0 = s_qw[c], wq1 = s_qw[16 + c], wk0 = s_kw[c], wk1 = s_kw[16 + c];
        qa0 = fmaf(wq0, xv[c].x, qa0);  qb0 = fmaf(wq0, xv[c].y, qb0);
        qa1 = fmaf(wq1, xv[c].x, qa1);  qb1 = fmaf(wq1, xv[c].y, qb1);
        ka0 = fmaf(wk0, xv[c].x, ka0);  kb0 = fmaf(wk0, xv[c].y, kb0);
        ka1 = fmaf(wk1, xv[c].x, ka1);  kb1 = fmaf(wk1, xv[c].y, kb1);
    }
    *(uint2*)&g_qh[p] = make_uint2(h2pack(qa0 * L2E, qa1 * L2E),
                                   h2pack(qb0 * L2E, qb1 * L2E));
    *(uint2*)&g_kh[p] = make_uint2(h2pack(ka0, ka1), h2pack(kb0, kb1));

    ull ava[8], avb[8];
#pragma unroll
    for (int j = 0; j < 8; j++) { ava[j] = s_vb[j]; avb[j] = s_vb[j]; }
#pragma unroll
    for (int c = 0; c < 16; c++) {
        ull xa = dup2(xv[c].x), xb = dup2(xv[c].y);
#pragma unroll
        for (int j = 0; j < 8; j++) {
            F2(ava[j], s_vw[c][j], xa, ava[j]);
            F2(avb[j], s_vw[c][j], xb, avb[j]);
        }
    }
    uint ha[8], hb[8];
#pragma unroll
    for (int j = 0; j < 8; j++) {
        float2 fa = unpack2(ava[j]), fb = unpack2(avb[j]);
        ha[j] = h2pack(fa.x, fa.y);
        hb[j] = h2pack(fb.x, fb.y);
    }
    uint4* vp = (uint4*)&g_vh[(size_t)p * 8];
    vp[0] = make_uint4(ha[0], ha[1], ha[2], ha[3]);
    vp[1] = make_uint4(ha[4], ha[5], ha[6], ha[7]);
    vp[2] = make_uint4(hb[0], hb[1], hb[2], hb[3]);
    vp[3] = make_uint4(hb[4], hb[5], hb[6], hb[7]);
}

// ---------------------------------------------------------------------------
// Shared-memory staging helper for V with interleaved layout:
//   sVh[rp*SVS + 2*c + hs] = half2 {v[2rp][ch], v[2rp+1][ch]}, ch = 8*hs + c
// so a single LDS.64 at (rp*SVS + 2*g) yields (b_lo: ch g, b_hi: ch 8+g).
// ---------------------------------------------------------------------------
__device__ __forceinline__ void stageV(uint* dstBase, uint4 e, uint4 o, int hs) {
    uint* dst = dstBase + hs;
    dst[0]  = __byte_perm(e.x, o.x, 0x5410);
    dst[2]  = __byte_perm(e.x, o.x, 0x7632);
    dst[4]  = __byte_perm(e.y, o.y, 0x5410);
    dst[6]  = __byte_perm(e.y, o.y, 0x7632);
    dst[8]  = __byte_perm(e.z, o.z, 0x5410);
    dst[10] = __byte_perm(e.z, o.z, 0x7632);
    dst[12] = __byte_perm(e.w, o.w, 0x5410);
    dst[14] = __byte_perm(e.w, o.w, 0x7632);
}

// ---------------------------------------------------------------------------
// Pass A: 2 column lines per block, 12 warps (6 per column).
// ---------------------------------------------------------------------------
__global__ __launch_bounds__(384) void passA_kernel()
{
    __shared__ __align__(8) uint s_qh[2][96];
    __shared__ __align__(8) uint s_kp[2][96];      // [col][rp*2 + {0:kx-pair,1:ky-pair}]
    __shared__ __align__(8) uint sVh[2][48 * SVS];

    int d = blockIdx.y, t = threadIdx.x;
    int w2 = blockIdx.x * 2;

    if (t < 192) {
        int cc = t / 96, row = t % 96;
        int p = d * HWn + row * Wn + w2 + cc;
        s_qh[cc][row] = g_qh[p];
        uint kh = g_kh[p];
        __half* kp = (__half*)s_kp[cc];
        int rp = row >> 1, b = row & 1;
        kp[rp * 4 + b]     = ((__half2*)&kh)->x;   // kx
        kp[rp * 4 + 2 + b] = ((__half2*)&kh)->y;   // ky
    } else {
        int t2 = t - 192;                 // 0..191
        int cc = t2 / 96, rem = t2 % 96;
        int rp = rem >> 1, hs = rem & 1;
        int pe = d * HWn + (2 * rp) * Wn + w2 + cc;
        int po = pe + Wn;
        uint4 e = *(const uint4*)&g_vh[(size_t)pe * 8 + hs * 4];
        uint4 o = *(const uint4*)&g_vh[(size_t)po * 8 + hs * 4];
        stageV(&sVh[cc][rp * SVS], e, o, hs);
    }
    __syncthreads();

    int warp = t >> 5, lane = t & 31, g = lane >> 2, tig = lane & 3;
    int col = warp / 6, warpIn = warp % 6;
    int lineBase = d * HWn + w2 + col;
    int r0 = warpIn * 16 + g, r1 = r0 + 8;

    uint qh0 = s_qh[col][r0], qh1 = s_qh[col][r1];
    uint qx0 = __byte_perm(qh0, qh0, 0x1010), qy0 = __byte_perm(qh0, qh0, 0x3232);
    uint qx1 = __byte_perm(qh1, qh1, 0x1010), qy1 = __byte_perm(qh1, qh1, 0x3232);

    float D0[4] = {0, 0, 0, 0};
    float D1[4] = {0, 0, 0, 0};
    float S[4]  = {0, 0, 0, 0};

#pragma unroll
    for (int kt = 0; kt < 6; kt++) {      // 16 keys per iteration
        int pi = kt * 8 + tig;            // key-pair index (cols 2pi, 2pi+1)
        ull kA = *(const ull*)&s_kp[col][pi * 2];          // {kx-pair, ky-pair}
        ull kB = *(const ull*)&s_kp[col][(pi + 4) * 2];
        uint kxA = (uint)kA, kyA = (uint)(kA >> 32);
        uint kxB = (uint)kB, kyB = (uint)(kB >> 32);

        uint a0 = ex2h2(hfma2(qx0, kxA, hmul2(qy0, kyA)));
        uint a1 = ex2h2(hfma2(qx1, kxA, hmul2(qy1, kyA)));
        uint a2 = ex2h2(hfma2(qx0, kxB, hmul2(qy0, kyB)));
        uint a3 = ex2h2(hfma2(qx1, kxB, hmul2(qy1, kyB)));

        int j0 = 2 * pi, j1 = 2 * (pi + 4);
        if (r0 == j0)     a0 &= 0xFFFF0000u;
        if (r0 == j0 + 1) a0 &= 0x0000FFFFu;
        if (r1 == j0)     a1 &= 0xFFFF0000u;
        if (r1 == j0 + 1) a1 &= 0x0000FFFFu;
        if (r0 == j1)     a2 &= 0xFFFF0000u;
        if (r0 == j1 + 1) a2 &= 0x0000FFFFu;
        if (r1 == j1)     a3 &= 0xFFFF0000u;
        if (r1 == j1 + 1) a3 &= 0x0000FFFFu;

        ull b0 = *(const ull*)&sVh[col][pi * SVS + 2 * g];        // {lo: ch g, hi: ch 8+g}
        ull b1 = *(const ull*)&sVh[col][(pi + 4) * SVS + 2 * g];
        uint b0lo = (uint)b0, b0hi = (uint)(b0 >> 32);
        uint b1lo = (uint)b1, b1hi = (uint)(b1 >> 32);

        mmah16(D0[0], D0[1], D0[2], D0[3], a0, a1, a2, a3, b0lo, b1lo);
        mmah16(D1[0], D1[1], D1[2], D1[3], a0, a1, a2, a3, b0hi, b1hi);
        mmah16(S[0],  S[1],  S[2],  S[3],  a0, a1, a2, a3, H2_ONES, H2_ONES);
    }

    int p0 = lineBase + r0 * Wn, p1 = lineBase + r1 * Wn;
    if (tig == 0) { g_sH[p0] = S[0]; g_sH[p1] = S[2]; }
    g_oh[(size_t)p0 * 8 + tig]     = h2pack(D0[0], D0[1]);
    g_oh[(size_t)p1 * 8 + tig]     = h2pack(D0[2], D0[3]);
    g_oh[(size_t)p0 * 8 + 4 + tig] = h2pack(D1[0], D1[1]);
    g_oh[(size_t)p1 * 8 + 4 + tig] = h2pack(D1[2], D1[3]);
}

// ---------------------------------------------------------------------------
// Pass B: one row line per block, 12 warps. Combine + residual.
// ---------------------------------------------------------------------------
__global__ __launch_bounds__(384) void passB_kernel(const float* __restrict__ xin,
                                                    float* __restrict__ dst,
                                                    const float* __restrict__ gammap)
{
    __shared__ __align__(8) uint s_qh[192];
    __shared__ __align__(8) uint s_kp[192];
    __shared__ __align__(8) uint sVh[96 * SVS];

    int d = blockIdx.y, h = blockIdx.x, t = threadIdx.x;
    int lineBase = d * HWn + h * Wn;
    const float* x = xin ? xin : g_y;
    float*       y = dst ? dst : g_y;

    if (t < 192) {
        int p = lineBase + t;
        s_qh[t] = g_qh[p];
        uint kh = g_kh[p];
        __half* kp = (__half*)s_kp;
        int rp = t >> 1, b = t & 1;
        kp[rp * 4 + b]     = ((__half2*)&kh)->x;
        kp[rp * 4 + 2 + b] = ((__half2*)&kh)->y;
    } else {
        int t2 = t - 192;                 // 0..191
        int rp = t2 >> 1, hs = t2 & 1;
        int pe = lineBase + 2 * rp;
        uint4 e = *(const uint4*)&g_vh[(size_t)pe * 8 + hs * 4];
        uint4 o = *(const uint4*)&g_vh[(size_t)(pe + 1) * 8 + hs * 4];
        stageV(&sVh[rp * SVS], e, o, hs);
    }

    int warp = t >> 5, lane = t & 31, g = lane >> 2, tig = lane & 3;
    int r0 = warp * 16 + g, r1 = r0 + 8;
    int p0 = lineBase + r0, p1 = lineBase + r1;

    // prefetch epilogue operands (overlap latency with mainloop)
    float sH0 = g_sH[p0], sH1 = g_sH[p1];
    uint oh00 = g_oh[(size_t)p0 * 8 + tig];
    uint oh01 = g_oh[(size_t)p0 * 8 + 4 + tig];
    uint oh10 = g_oh[(size_t)p1 * 8 + tig];
    uint oh11 = g_oh[(size_t)p1 * 8 + 4 + tig];
    float gamma = gammap[0];

    __syncthreads();

    uint qh0 = s_qh[r0], qh1 = s_qh[r1];
    uint qx0 = __byte_perm(qh0, qh0, 0x1010), qy0 = __byte_perm(qh0, qh0, 0x3232);
    uint qx1 = __byte_perm(qh1, qh1, 0x1010), qy1 = __byte_perm(qh1, qh1, 0x3232);

    float D0[4] = {0, 0, 0, 0};
    float D1[4] = {0, 0, 0, 0};
    float S[4]  = {0, 0, 0, 0};

#pragma unroll
    for (int kt = 0; kt < 12; kt++) {     // 16 keys per iteration
        int pi = kt * 8 + tig;
        ull kA = *(const ull*)&s_kp[pi * 2];
        ull kB = *(const ull*)&s_kp[(pi + 4) * 2];
        uint kxA = (uint)kA, kyA = (uint)(kA >> 32);
        uint kxB = (uint)kB, kyB = (uint)(kB >> 32);

        uint a0 = ex2h2(hfma2(qx0, kxA, hmul2(qy0, kyA)));
        uint a1 = ex2h2(hfma2(qx1, kxA, hmul2(qy1, kyA)));
        uint a2 = ex2h2(hfma2(qx0, kxB, hmul2(qy0, kyB)));
        uint a3 = ex2h2(hfma2(qx1, kxB, hmul2(qy1, kyB)));

        ull b0 = *(const ull*)&sVh[pi * SVS + 2 * g];
        ull b1 = *(const ull*)&sVh[(pi + 4) * SVS + 2 * g];
        uint b0lo = (uint)b0, b0hi = (uint)(b0 >> 32);
        uint b1lo = (uint)b1, b1hi = (uint)(b1 >> 32);

        mmah16(D0[0], D0[1], D0[2], D0[3], a0, a1, a2, a3, b0lo, b1lo);
        mmah16(D1[0], D1[1], D1[2], D1[3], a0, a1, a2, a3, b0hi, b1hi);
        mmah16(S[0],  S[1],  S[2],  S[3],  a0, a1, a2, a3, H2_ONES, H2_ONES);
    }

    float inv0 = __fdividef(gamma, S[0] + sH0);
    float inv1 = __fdividef(gamma, S[2] + sH1);

    {
        float2 oh0 = h2unpack(oh00);
        float2 oh1 = h2unpack(oh10);
        int c = 2 * tig;
        y[c * Pn + p0]       = x[c * Pn + p0]       + (D0[0] + oh0.x) * inv0;
        y[(c + 1) * Pn + p0] = x[(c + 1) * Pn + p0] + (D0[1] + oh0.y) * inv0;
        y[c * Pn + p1]       = x[c * Pn + p1]       + (D0[2] + oh1.x) * inv1;
        y[(c + 1) * Pn + p1] = x[(c + 1) * Pn + p1] + (D0[3] + oh1.y) * inv1;
    }
    {
        float2 oh0 = h2unpack(oh01);
        float2 oh1 = h2unpack(oh11);
        int c = 8 + 2 * tig;
        y[c * Pn + p0]       = x[c * Pn + p0]       + (D1[0] + oh0.x) * inv0;
        y[(c + 1) * Pn + p0] = x[(c + 1) * Pn + p0] + (D1[1] + oh0.y) * inv0;
        y[c * Pn + p1]       = x[c * Pn + p1]       + (D1[2] + oh1.x) * inv1;
        y[(c + 1) * Pn + p1] = x[(c + 1) * Pn + p1] + (D1[3] + oh1.y) * inv1;
    }
}

// ---------------------------------------------------------------------------
extern "C" void kernel_launch(void* const* d_in, const int* in_sizes, int n_in,
                              void* d_out, int out_size)
{
    const float* x     = (const float*)d_in[0];
    const float* qw    = (const float*)d_in[1];
    const float* qb    = (const float*)d_in[2];
    const float* kw    = (const float*)d_in[3];
    const float* kb    = (const float*)d_in[4];
    const float* vw    = (const float*)d_in[5];
    const float* vb    = (const float*)d_in[6];
    const float* gamma = (const float*)d_in[7];
    float* out = (float*)d_out;

    dim3 gA(Wn / 2, Dn);   // 96 x 24 blocks, 384 threads
    dim3 gB(Hn, Dn);       // 96 x 24 blocks, 384 threads
    int qkvBlocks = Pn / 256;

    qkv_kernel<<<qkvBlocks, 128>>>(x, qw, qb, kw, kb, vw, vb);
    passA_kernel<<<gA, 384>>>();
    passB_kernel<<<gB, 384>>>(x, nullptr, gamma);

    qkv_kernel<<<qkvBlocks, 128>>>(nullptr, qw, qb, kw, kb, vw, vb);
    passA_kernel<<<gA, 384>>>();
    passB_kernel<<<gB, 384>>>(nullptr, out, gamma);
}

// round 13
// speedup vs baseline: 1.1699x; 1.0126x over previous
#include <cuda_runtime.h>
#include <cuda_fp16.h>

#define Dn 24
#define Hn 96
#define Wn 192
#define HWn (Hn * Wn)          // 18432
#define Pn (Dn * HWn)          // 442368

typedef unsigned long long ull;
typedef unsigned int uint;

#define H2_ONES 0x3C003C00u    // half2 {1, 1}
#define SVS 40                 // sVh rowpair stride (uints)

// Scratch (device globals — allocation forbidden)
__device__ uint  g_qh[Pn];         // half2 {qx,qy}, q pre-scaled by log2(e)
__device__ uint  g_kh[Pn];         // half2 {kx,ky}
__device__ uint  g_vh[Pn * 8];     // [p][8] half2: channels (2j, 2j+1)
__device__ float g_y[Pn * 16];     // intermediate image, [c][p]
__device__ float g_sH[Pn];
__device__ uint  g_oh[Pn * 8];     // unnormalized out_H, half2 channel pairs

// ---- helpers ---------------------------------------------------------------
__device__ __forceinline__ void F2(ull& d, ull a, ull b, ull c) {
    asm("fma.rn.f32x2 %0,%1,%2,%3;" : "=l"(d) : "l"(a), "l"(b), "l"(c));
}
__device__ __forceinline__ ull pack2(float lo, float hi) {
    ull r; asm("mov.b64 %0,{%1,%2};" : "=l"(r) : "f"(lo), "f"(hi)); return r;
}
__device__ __forceinline__ ull dup2(float v) { return pack2(v, v); }
__device__ __forceinline__ float2 unpack2(ull v) {
    float2 r; asm("mov.b64 {%0,%1},%2;" : "=f"(r.x), "=f"(r.y) : "l"(v)); return r;
}
__device__ __forceinline__ uint h2pack(float lo, float hi) {   // {lo, hi}
    uint u; asm("cvt.rn.f16x2.f32 %0,%1,%2;" : "=r"(u) : "f"(hi), "f"(lo)); return u;
}
__device__ __forceinline__ uint ex2h2(uint e) {                // 2 exps, 1 MUFU op
    uint r; asm("ex2.approx.f16x2 %0,%1;" : "=r"(r) : "r"(e)); return r;
}
__device__ __forceinline__ uint hmul2(uint a, uint b) {
    uint d; asm("mul.f16x2 %0,%1,%2;" : "=r"(d) : "r"(a), "r"(b)); return d;
}
__device__ __forceinline__ uint hfma2(uint a, uint b, uint c) {
    uint d; asm("fma.rn.f16x2 %0,%1,%2,%3;" : "=r"(d) : "r"(a), "r"(b), "r"(c)); return d;
}
__device__ __forceinline__ float2 h2unpack(uint u) {
    __half2 h = *reinterpret_cast<__half2*>(&u);
    return __half22float2(h);
}
__device__ __forceinline__ void mmah16(float& d0, float& d1, float& d2, float& d3,
                                       uint a0, uint a1, uint a2, uint a3,
                                       uint b0, uint b1) {
    asm("mma.sync.aligned.m16n8k16.row.col.f32.f16.f16.f32 "
        "{%0,%1,%2,%3},{%4,%5,%6,%7},{%8,%9},{%0,%1,%2,%3};"
        : "+f"(d0), "+f"(d1), "+f"(d2), "+f"(d3)
        : "r"(a0), "r"(a1), "r"(a2), "r"(a3), "r"(b0), "r"(b1));
}

#define L2E 1.44269504088896340736f

// ---------------------------------------------------------------------------
// QKV projection: 4 pixels/thread, float4 x-loads; q,k,v stored fp16.
// ---------------------------------------------------------------------------
__global__ __launch_bounds__(128) void qkv_kernel(const float* __restrict__ xin,
                           const float* __restrict__ qw, const float* __restrict__ qb,
                           const float* __restrict__ kw, const float* __restrict__ kb,
                           const float* __restrict__ vw, const float* __restrict__ vb)
{
    __shared__ float s_qw[32], s_kw[32], s_qb[2], s_kb[2];
    __shared__ ull s_vw[16][8];
    __shared__ ull s_vb[8];
    const float* x = xin ? xin : g_y;

    int t = threadIdx.x;
    {
        int c = t & 15, j = t >> 4;
        s_vw[c][j] = pack2(vw[(2 * j) * 16 + c], vw[(2 * j + 1) * 16 + c]);
    }
    if (t < 32)       s_qw[t]      = qw[t];
    else if (t < 64)  s_kw[t - 32] = kw[t - 32];
    else if (t < 66)  s_qb[t - 64] = qb[t - 64];
    else if (t < 68)  s_kb[t - 66] = kb[t - 66];
    else if (t < 76)  s_vb[t - 68] = pack2(vb[2 * (t - 68)], vb[2 * (t - 68) + 1]);
    __syncthreads();

    int p = blockIdx.x * 512 + 4 * t;   // 4 consecutive pixels

    float q0[4], q1[4], k0[4], k1[4];
#pragma unroll
    for (int i = 0; i < 4; i++) {
        q0[i] = s_qb[0]; q1[i] = s_qb[1];
        k0[i] = s_kb[0]; k1[i] = s_kb[1];
    }
    ull av[4][8];
#pragma unroll
    for (int i = 0; i < 4; i++)
#pragma unroll
        for (int j = 0; j < 8; j++) av[i][j] = s_vb[j];

#pragma unroll
    for (int c = 0; c < 16; c++) {
        float4 xv = *(const float4*)&x[c * Pn + p];
        float wq0 = s_qw[c], wq1 = s_qw[16 + c], wk0 = s_kw[c], wk1 = s_kw[16 + c];
        float xs[4] = { xv.x, xv.y, xv.z, xv.w };
#pragma unroll
        for (int i = 0; i < 4; i++) {
            q0[i] = fmaf(wq0, xs[i], q0[i]);
            q1[i] = fmaf(wq1, xs[i], q1[i]);
            k0[i] = fmaf(wk0, xs[i], k0[i]);
            k1[i] = fmaf(wk1, xs[i], k1[i]);
        }
#pragma unroll
        for (int i = 0; i < 4; i++) {
            ull xc = dup2(xs[i]);
#pragma unroll
            for (int j = 0; j < 8; j++) F2(av[i][j], s_vw[c][j], xc, av[i][j]);
        }
    }

    *(uint4*)&g_qh[p] = make_uint4(h2pack(q0[0] * L2E, q1[0] * L2E),
                                   h2pack(q0[1] * L2E, q1[1] * L2E),
                                   h2pack(q0[2] * L2E, q1[2] * L2E),
                                   h2pack(q0[3] * L2E, q1[3] * L2E));
    *(uint4*)&g_kh[p] = make_uint4(h2pack(k0[0], k1[0]), h2pack(k0[1], k1[1]),
                                   h2pack(k0[2], k1[2]), h2pack(k0[3], k1[3]));

#pragma unroll
    for (int i = 0; i < 4; i++) {
        uint h[8];
#pragma unroll
        for (int j = 0; j < 8; j++) {
            float2 f = unpack2(av[i][j]);
            h[j] = h2pack(f.x, f.y);
        }
        uint4* vp = (uint4*)&g_vh[(size_t)(p + i) * 8];
        vp[0] = make_uint4(h[0], h[1], h[2], h[3]);
        vp[1] = make_uint4(h[4], h[5], h[6], h[7]);
    }
}

// ---------------------------------------------------------------------------
// V staging: sVh[rp*SVS + 2*c + hs] = half2 {v[2rp][ch], v[2rp+1][ch]}, ch=8hs+c
// ---------------------------------------------------------------------------
__device__ __forceinline__ void stageV(uint* dstBase, uint4 e, uint4 o, int hs) {
    uint* dst = dstBase + hs;
    dst[0]  = __byte_perm(e.x, o.x, 0x5410);
    dst[2]  = __byte_perm(e.x, o.x, 0x7632);
    dst[4]  = __byte_perm(e.y, o.y, 0x5410);
    dst[6]  = __byte_perm(e.y, o.y, 0x7632);
    dst[8]  = __byte_perm(e.z, o.z, 0x5410);
    dst[10] = __byte_perm(e.z, o.z, 0x7632);
    dst[12] = __byte_perm(e.w, o.w, 0x5410);
    dst[14] = __byte_perm(e.w, o.w, 0x7632);
}

// ---------------------------------------------------------------------------
// Pass A: 4 column lines per block, 768 threads / 24 warps (6 per column).
// Coalesced prologue: uint4 q/k per row; 8 consecutive V tasks = 1 line.
// ---------------------------------------------------------------------------
__global__ __launch_bounds__(768) void passA_kernel()
{
    __shared__ __align__(16) uint s_qh[4][96];
    __shared__ __align__(8)  uint s_kp[4][96];     // per col: half[rp*4 + {b, 2+b}]
    __shared__ __align__(8)  uint sVh[4][48 * SVS];

    int d = blockIdx.y, t = threadIdx.x;
    int w4 = blockIdx.x * 4;
    int base = d * HWn + w4;

    if (t < 96) {
        uint4 qq = *(const uint4*)&g_qh[base + t * Wn];
        s_qh[0][t] = qq.x; s_qh[1][t] = qq.y; s_qh[2][t] = qq.z; s_qh[3][t] = qq.w;
    } else if (t < 192) {
        int row = t - 96;
        uint4 kk = *(const uint4*)&g_kh[base + row * Wn];
        int rp = row >> 1, b = row & 1;
        uint kv[4] = { kk.x, kk.y, kk.z, kk.w };
#pragma unroll
        for (int cc = 0; cc < 4; cc++) {
            __half2 h = *(__half2*)&kv[cc];
            __half* kp = (__half*)s_kp[cc];
            kp[rp * 4 + b]     = h.x;   // kx
            kp[rp * 4 + 2 + b] = h.y;   // ky
        }
    } else if (t >= 384) {
        int task = t - 384;               // 0..383
        int rp = task >> 3, hs = (task >> 2) & 1, cc = task & 3;
        int pe = base + (2 * rp) * Wn + cc;
        int po = pe + Wn;
        uint4 e = *(const uint4*)&g_vh[(size_t)pe * 8 + hs * 4];
        uint4 o = *(const uint4*)&g_vh[(size_t)po * 8 + hs * 4];
        stageV(&sVh[cc][rp * SVS], e, o, hs);
    }
    __syncthreads();

    int warp = t >> 5, lane = t & 31, g = lane >> 2, tig = lane & 3;
    int col = warp / 6, warpIn = warp % 6;
    int lineBase = base + col;
    int r0 = warpIn * 16 + g, r1 = r0 + 8;

    uint qh0 = s_qh[col][r0], qh1 = s_qh[col][r1];
    uint qx0 = __byte_perm(qh0, qh0, 0x1010), qy0 = __byte_perm(qh0, qh0, 0x3232);
    uint qx1 = __byte_perm(qh1, qh1, 0x1010), qy1 = __byte_perm(qh1, qh1, 0x3232);

    float D0[4] = {0, 0, 0, 0};
    float D1[4] = {0, 0, 0, 0};
    float S[4]  = {0, 0, 0, 0};

#pragma unroll
    for (int kt = 0; kt < 6; kt++) {      // 16 keys per iteration
        int pi = kt * 8 + tig;            // key-pair index (cols 2pi, 2pi+1)
        ull kA = *(const ull*)&s_kp[col][pi * 2];
        ull kB = *(const ull*)&s_kp[col][(pi + 4) * 2];
        uint kxA = (uint)kA, kyA = (uint)(kA >> 32);
        uint kxB = (uint)kB, kyB = (uint)(kB >> 32);

        uint a0 = ex2h2(hfma2(qx0, kxA, hmul2(qy0, kyA)));
        uint a1 = ex2h2(hfma2(qx1, kxA, hmul2(qy1, kyA)));
        uint a2 = ex2h2(hfma2(qx0, kxB, hmul2(qy0, kyB)));
        uint a3 = ex2h2(hfma2(qx1, kxB, hmul2(qy1, kyB)));

        int j0 = 2 * pi, j1 = 2 * (pi + 4);
        if (r0 == j0)     a0 &= 0xFFFF0000u;
        if (r0 == j0 + 1) a0 &= 0x0000FFFFu;
        if (r1 == j0)     a1 &= 0xFFFF0000u;
        if (r1 == j0 + 1) a1 &= 0x0000FFFFu;
        if (r0 == j1)     a2 &= 0xFFFF0000u;
        if (r0 == j1 + 1) a2 &= 0x0000FFFFu;
        if (r1 == j1)     a3 &= 0xFFFF0000u;
        if (r1 == j1 + 1) a3 &= 0x0000FFFFu;

        ull b0 = *(const ull*)&sVh[col][pi * SVS + 2 * g];
        ull b1 = *(const ull*)&sVh[col][(pi + 4) * SVS + 2 * g];
        uint b0lo = (uint)b0, b0hi = (uint)(b0 >> 32);
        uint b1lo = (uint)b1, b1hi = (uint)(b1 >> 32);

        mmah16(D0[0], D0[1], D0[2], D0[3], a0, a1, a2, a3, b0lo, b1lo);
        mmah16(D1[0], D1[1], D1[2], D1[3], a0, a1, a2, a3, b0hi, b1hi);
        mmah16(S[0],  S[1],  S[2],  S[3],  a0, a1, a2, a3, H2_ONES, H2_ONES);
    }

    int p0 = lineBase + r0 * Wn, p1 = lineBase + r1 * Wn;
    if (tig == 0) { g_sH[p0] = S[0]; g_sH[p1] = S[2]; }
    g_oh[(size_t)p0 * 8 + tig]     = h2pack(D0[0], D0[1]);
    g_oh[(size_t)p1 * 8 + tig]     = h2pack(D0[2], D0[3]);
    g_oh[(size_t)p0 * 8 + 4 + tig] = h2pack(D1[0], D1[1]);
    g_oh[(size_t)p1 * 8 + 4 + tig] = h2pack(D1[2], D1[3]);
}

// ---------------------------------------------------------------------------
// Pass B: one row line per block, 12 warps. Combine + residual. (unchanged)
// ---------------------------------------------------------------------------
__global__ __launch_bounds__(384) void passB_kernel(const float* __restrict__ xin,
                                                    float* __restrict__ dst,
                                                    const float* __restrict__ gammap)
{
    __shared__ __align__(8) uint s_qh[192];
    __shared__ __align__(8) uint s_kp[192];
    __shared__ __align__(8) uint sVh[96 * SVS];

    int d = blockIdx.y, h = blockIdx.x, t = threadIdx.x;
    int lineBase = d * HWn + h * Wn;
    const float* x = xin ? xin : g_y;
    float*       y = dst ? dst : g_y;

    if (t < 192) {
        int p = lineBase + t;
        s_qh[t] = g_qh[p];
        uint kh = g_kh[p];
        __half* kp = (__half*)s_kp;
        int rp = t >> 1, b = t & 1;
        kp[rp * 4 + b]     = ((__half2*)&kh)->x;
        kp[rp * 4 + 2 + b] = ((__half2*)&kh)->y;
    } else {
        int t2 = t - 192;                 // 0..191
        int rp = t2 >> 1, hs = t2 & 1;
        int pe = lineBase + 2 * rp;
        uint4 e = *(const uint4*)&g_vh[(size_t)pe * 8 + hs * 4];
        uint4 o = *(const uint4*)&g_vh[(size_t)(pe + 1) * 8 + hs * 4];
        stageV(&sVh[rp * SVS], e, o, hs);
    }

    int warp = t >> 5, lane = t & 31, g = lane >> 2, tig = lane & 3;
    int r0 = warp * 16 + g, r1 = r0 + 8;
    int p0 = lineBase + r0, p1 = lineBase + r1;

    float sH0 = g_sH[p0], sH1 = g_sH[p1];
    uint oh00 = g_oh[(size_t)p0 * 8 + tig];
    uint oh01 = g_oh[(size_t)p0 * 8 + 4 + tig];
    uint oh10 = g_oh[(size_t)p1 * 8 + tig];
    uint oh11 = g_oh[(size_t)p1 * 8 + 4 + tig];
    float gamma = gammap[0];

    __syncthreads();

    uint qh0 = s_qh[r0], qh1 = s_qh[r1];
    uint qx0 = __byte_perm(qh0, qh0, 0x1010), qy0 = __byte_perm(qh0, qh0, 0x3232);
    uint qx1 = __byte_perm(qh1, qh1, 0x1010), qy1 = __byte_perm(qh1, qh1, 0x3232);

    float D0[4] = {0, 0, 0, 0};
    float D1[4] = {0, 0, 0, 0};
    float S[4]  = {0, 0, 0, 0};

#pragma unroll
    for (int kt = 0; kt < 12; kt++) {     // 16 keys per iteration
        int pi = kt * 8 + tig;
        ull kA = *(const ull*)&s_kp[pi * 2];
        ull kB = *(const ull*)&s_kp[(pi + 4) * 2];
        uint kxA = (uint)kA, kyA = (uint)(kA >> 32);
        uint kxB = (uint)kB, kyB = (uint)(kB >> 32);

        uint a0 = ex2h2(hfma2(qx0, kxA, hmul2(qy0, kyA)));
        uint a1 = ex2h2(hfma2(qx1, kxA, hmul2(qy1, kyA)));
        uint a2 = ex2h2(hfma2(qx0, kxB, hmul2(qy0, kyB)));
        uint a3 = ex2h2(hfma2(qx1, kxB, hmul2(qy1, kyB)));

        ull b0 = *(const ull*)&sVh[pi * SVS + 2 * g];
        ull b1 = *(const ull*)&sVh[(pi + 4) * SVS + 2 * g];
        uint b0lo = (uint)b0, b0hi = (uint)(b0 >> 32);
        uint b1lo = (uint)b1, b1hi = (uint)(b1 >> 32);

        mmah16(D0[0], D0[1], D0[2], D0[3], a0, a1, a2, a3, b0lo, b1lo);
        mmah16(D1[0], D1[1], D1[2], D1[3], a0, a1, a2, a3, b0hi, b1hi);
        mmah16(S[0],  S[1],  S[2],  S[3],  a0, a1, a2, a3, H2_ONES, H2_ONES);
    }

    float inv0 = __fdividef(gamma, S[0] + sH0);
    float inv1 = __fdividef(gamma, S[2] + sH1);

    {
        float2 oh0 = h2unpack(oh00);
        float2 oh1 = h2unpack(oh10);
        int c = 2 * tig;
        y[c * Pn + p0]       = x[c * Pn + p0]       + (D0[0] + oh0.x) * inv0;
        y[(c + 1) * Pn + p0] = x[(c + 1) * Pn + p0] + (D0[1] + oh0.y) * inv0;
        y[c * Pn + p1]       = x[c * Pn + p1]       + (D0[2] + oh1.x) * inv1;
        y[(c + 1) * Pn + p1] = x[(c + 1) * Pn + p1] + (D0[3] + oh1.y) * inv1;
    }
    {
        float2 oh0 = h2unpack(oh01);
        float2 oh1 = h2unpack(oh11);
        int c = 8 + 2 * tig;
        y[c * Pn + p0]       = x[c * Pn + p0]       + (D1[0] + oh0.x) * inv0;
        y[(c + 1) * Pn + p0] = x[(c + 1) * Pn + p0] + (D1[1] + oh0.y) * inv0;
        y[c * Pn + p1]       = x[c * Pn + p1]       + (D1[2] + oh1.x) * inv1;
        y[(c + 1) * Pn + p1] = x[(c + 1) * Pn + p1] + (D1[3] + oh1.y) * inv1;
    }
}

// ---------------------------------------------------------------------------
extern "C" void kernel_launch(void* const* d_in, const int* in_sizes, int n_in,
                              void* d_out, int out_size)
{
    const float* x     = (const float*)d_in[0];
    const float* qw    = (const float*)d_in[1];
    const float* qb    = (const float*)d_in[2];
    const float* kw    = (const float*)d_in[3];
    const float* kb    = (const float*)d_in[4];
    const float* vw    = (const float*)d_in[5];
    const float* vb    = (const float*)d_in[6];
    const float* gamma = (const float*)d_in[7];
    float* out = (float*)d_out;

    dim3 gA(Wn / 4, Dn);   // 48 x 24 blocks, 768 threads (4 column lines each)
    dim3 gB(Hn, Dn);       // 96 x 24 blocks, 384 threads
    int qkvBlocks = Pn / 512;   // 864

    qkv_kernel<<<qkvBlocks, 128>>>(x, qw, qb, kw, kb, vw, vb);
    passA_kernel<<<gA, 768>>>();
    passB_kernel<<<gB, 384>>>(x, nullptr, gamma);

    qkv_kernel<<<qkvBlocks, 128>>>(nullptr, qw, qb, kw, kb, vw, vb);
    passA_kernel<<<gA, 768>>>();
    passB_kernel<<<gB, 384>>>(nullptr, out, gamma);
}

// round 14
// speedup vs baseline: 1.2097x; 1.0340x over previous
#include <cuda_runtime.h>
#include <cuda_fp16.h>

#define Dn 24
#define Hn 96
#define Wn 192
#define HWn (Hn * Wn)          // 18432
#define Pn (Dn * HWn)          // 442368

typedef unsigned long long ull;
typedef unsigned int uint;

#define H2_ONES 0x3C003C00u    // half2 {1, 1}
#define SVS 40                 // sVh rowpair stride (uints)

// Scratch (device globals — allocation forbidden)
__device__ uint  g_qh[Pn];         // half2 {qx,qy}, q pre-scaled by log2(e)
__device__ uint  g_kh[Pn];         // half2 {kx,ky}
__device__ uint  g_vh[Pn * 8];     // [p][8] half2: channels (2j, 2j+1)
__device__ uint  g_yres[Pn * 8];   // fp16 intermediate image, pixel-major ch pairs
__device__ float g_sH[Pn];
__device__ uint  g_oh[Pn * 8];     // unnormalized out_H, half2 channel pairs

// ---- helpers ---------------------------------------------------------------
__device__ __forceinline__ void F2(ull& d, ull a, ull b, ull c) {
    asm("fma.rn.f32x2 %0,%1,%2,%3;" : "=l"(d) : "l"(a), "l"(b), "l"(c));
}
__device__ __forceinline__ ull pack2(float lo, float hi) {
    ull r; asm("mov.b64 %0,{%1,%2};" : "=l"(r) : "f"(lo), "f"(hi)); return r;
}
__device__ __forceinline__ ull dup2(float v) { return pack2(v, v); }
__device__ __forceinline__ float2 unpack2(ull v) {
    float2 r; asm("mov.b64 {%0,%1},%2;" : "=f"(r.x), "=f"(r.y) : "l"(v)); return r;
}
__device__ __forceinline__ uint h2pack(float lo, float hi) {   // {lo, hi}
    uint u; asm("cvt.rn.f16x2.f32 %0,%1,%2;" : "=r"(u) : "f"(hi), "f"(lo)); return u;
}
__device__ __forceinline__ uint ex2h2(uint e) {                // 2 exps, 1 MUFU op
    uint r; asm("ex2.approx.f16x2 %0,%1;" : "=r"(r) : "r"(e)); return r;
}
__device__ __forceinline__ uint hmul2(uint a, uint b) {
    uint d; asm("mul.f16x2 %0,%1,%2;" : "=r"(d) : "r"(a), "r"(b)); return d;
}
__device__ __forceinline__ uint hfma2(uint a, uint b, uint c) {
    uint d; asm("fma.rn.f16x2 %0,%1,%2,%3;" : "=r"(d) : "r"(a), "r"(b), "r"(c)); return d;
}
__device__ __forceinline__ float2 h2unpack(uint u) {
    __half2 h = *reinterpret_cast<__half2*>(&u);
    return __half22float2(h);
}
__device__ __forceinline__ void mmah16(float& d0, float& d1, float& d2, float& d3,
                                       uint a0, uint a1, uint a2, uint a3,
                                       uint b0, uint b1) {
    asm("mma.sync.aligned.m16n8k16.row.col.f32.f16.f16.f32 "
        "{%0,%1,%2,%3},{%4,%5,%6,%7},{%8,%9},{%0,%1,%2,%3};"
        : "+f"(d0), "+f"(d1), "+f"(d2), "+f"(d3)
        : "r"(a0), "r"(a1), "r"(a2), "r"(a3), "r"(b0), "r"(b1));
}

#define L2E 1.44269504088896340736f

// ---------------------------------------------------------------------------
// QKV projection: 2 pixels/thread. Input from fp32 x (iter1) or fp16
// pixel-major g_yres (iter2). q,k,v stored fp16.
// ---------------------------------------------------------------------------
__global__ __launch_bounds__(128) void qkv_kernel(const float* __restrict__ xin,
                           const float* __restrict__ qw, const float* __restrict__ qb,
                           const float* __restrict__ kw, const float* __restrict__ kb,
                           const float* __restrict__ vw, const float* __restrict__ vb)
{
    __shared__ float s_qw[32], s_kw[32], s_qb[2], s_kb[2];
    __shared__ ull s_vw[16][8];
    __shared__ ull s_vb[8];

    int t = threadIdx.x;
    {
        int c = t & 15, j = t >> 4;
        s_vw[c][j] = pack2(vw[(2 * j) * 16 + c], vw[(2 * j + 1) * 16 + c]);
    }
    if (t < 32)       s_qw[t]      = qw[t];
    else if (t < 64)  s_kw[t - 32] = kw[t - 32];
    else if (t < 66)  s_qb[t - 64] = qb[t - 64];
    else if (t < 68)  s_kb[t - 66] = kb[t - 66];
    else if (t < 76)  s_vb[t - 68] = pack2(vb[2 * (t - 68)], vb[2 * (t - 68) + 1]);
    __syncthreads();

    int p = blockIdx.x * 256 + 2 * t;   // 2 consecutive pixels

    float2 xv[16];                      // .x = pixel p, .y = pixel p+1
    if (xin) {
#pragma unroll
        for (int c = 0; c < 16; c++) xv[c] = *(const float2*)&xin[c * Pn + p];
    } else {
        const uint4* ya = (const uint4*)&g_yres[(size_t)p * 8];
        uint4 a0 = ya[0], a1 = ya[1], b0 = ya[2], b1 = ya[3];
        uint ua[8] = { a0.x, a0.y, a0.z, a0.w, a1.x, a1.y, a1.z, a1.w };
        uint ub[8] = { b0.x, b0.y, b0.z, b0.w, b1.x, b1.y, b1.z, b1.w };
#pragma unroll
        for (int j = 0; j < 8; j++) {
            float2 fa = h2unpack(ua[j]);   // {ch2j, ch2j+1} of pixel p
            float2 fb = h2unpack(ub[j]);   // of pixel p+1
            xv[2 * j]     = make_float2(fa.x, fb.x);
            xv[2 * j + 1] = make_float2(fa.y, fb.y);
        }
    }

    float qa0 = s_qb[0], qa1 = s_qb[1], ka0 = s_kb[0], ka1 = s_kb[1];
    float qb0 = s_qb[0], qb1 = s_qb[1], kb0 = s_kb[0], kb1 = s_kb[1];
#pragma unroll
    for (int c = 0; c < 16; c++) {
        float wq0 = s_qw[c], wq1 = s_qw[16 + c], wk0 = s_kw[c], wk1 = s_kw[16 + c];
        qa0 = fmaf(wq0, xv[c].x, qa0);  qb0 = fmaf(wq0, xv[c].y, qb0);
        qa1 = fmaf(wq1, xv[c].x, qa1);  qb1 = fmaf(wq1, xv[c].y, qb1);
        ka0 = fmaf(wk0, xv[c].x, ka0);  kb0 = fmaf(wk0, xv[c].y, kb0);
        ka1 = fmaf(wk1, xv[c].x, ka1);  kb1 = fmaf(wk1, xv[c].y, kb1);
    }
    *(uint2*)&g_qh[p] = make_uint2(h2pack(qa0 * L2E, qa1 * L2E),
                                   h2pack(qb0 * L2E, qb1 * L2E));
    *(uint2*)&g_kh[p] = make_uint2(h2pack(ka0, ka1), h2pack(kb0, kb1));

    ull ava[8], avb[8];
#pragma unroll
    for (int j = 0; j < 8; j++) { ava[j] = s_vb[j]; avb[j] = s_vb[j]; }
#pragma unroll
    for (int c = 0; c < 16; c++) {
        ull xa = dup2(xv[c].x), xb = dup2(xv[c].y);
#pragma unroll
        for (int j = 0; j < 8; j++) {
            F2(ava[j], s_vw[c][j], xa, ava[j]);
            F2(avb[j], s_vw[c][j], xb, avb[j]);
        }
    }
    uint ha[8], hb[8];
#pragma unroll
    for (int j = 0; j < 8; j++) {
        float2 fa = unpack2(ava[j]), fb = unpack2(avb[j]);
        ha[j] = h2pack(fa.x, fa.y);
        hb[j] = h2pack(fb.x, fb.y);
    }
    uint4* vp = (uint4*)&g_vh[(size_t)p * 8];
    vp[0] = make_uint4(ha[0], ha[1], ha[2], ha[3]);
    vp[1] = make_uint4(ha[4], ha[5], ha[6], ha[7]);
    vp[2] = make_uint4(hb[0], hb[1], hb[2], hb[3]);
    vp[3] = make_uint4(hb[4], hb[5], hb[6], hb[7]);
}

// ---------------------------------------------------------------------------
// V staging: sVh[rp*SVS + 2*c + hs] = half2 {v[2rp][ch], v[2rp+1][ch]}, ch=8hs+c
// ---------------------------------------------------------------------------
__device__ __forceinline__ void stageV(uint* dstBase, uint4 e, uint4 o, int hs) {
    uint* dst = dstBase + hs;
    dst[0]  = __byte_perm(e.x, o.x, 0x5410);
    dst[2]  = __byte_perm(e.x, o.x, 0x7632);
    dst[4]  = __byte_perm(e.y, o.y, 0x5410);
    dst[6]  = __byte_perm(e.y, o.y, 0x7632);
    dst[8]  = __byte_perm(e.z, o.z, 0x5410);
    dst[10] = __byte_perm(e.z, o.z, 0x7632);
    dst[12] = __byte_perm(e.w, o.w, 0x5410);
    dst[14] = __byte_perm(e.w, o.w, 0x7632);
}

// ---------------------------------------------------------------------------
// Pass A: 4 column lines per block, 768 threads / 24 warps (6 per column).
// ---------------------------------------------------------------------------
__global__ __launch_bounds__(768) void passA_kernel()
{
    __shared__ __align__(16) uint s_qh[4][96];
    __shared__ __align__(8)  uint s_kp[4][96];
    __shared__ __align__(8)  uint sVh[4][48 * SVS];

    int d = blockIdx.y, t = threadIdx.x;
    int w4 = blockIdx.x * 4;
    int base = d * HWn + w4;

    if (t < 96) {
        uint4 qq = *(const uint4*)&g_qh[base + t * Wn];
        s_qh[0][t] = qq.x; s_qh[1][t] = qq.y; s_qh[2][t] = qq.z; s_qh[3][t] = qq.w;
    } else if (t < 192) {
        int row = t - 96;
        uint4 kk = *(const uint4*)&g_kh[base + row * Wn];
        int rp = row >> 1, b = row & 1;
        uint kv[4] = { kk.x, kk.y, kk.z, kk.w };
#pragma unroll
        for (int cc = 0; cc < 4; cc++) {
            __half2 h = *(__half2*)&kv[cc];
            __half* kp = (__half*)s_kp[cc];
            kp[rp * 4 + b]     = h.x;
            kp[rp * 4 + 2 + b] = h.y;
        }
    } else if (t >= 384) {
        int task = t - 384;               // 0..383
        int rp = task >> 3, hs = (task >> 2) & 1, cc = task & 3;
        int pe = base + (2 * rp) * Wn + cc;
        int po = pe + Wn;
        uint4 e = *(const uint4*)&g_vh[(size_t)pe * 8 + hs * 4];
        uint4 o = *(const uint4*)&g_vh[(size_t)po * 8 + hs * 4];
        stageV(&sVh[cc][rp * SVS], e, o, hs);
    }
    __syncthreads();

    int warp = t >> 5, lane = t & 31, g = lane >> 2, tig = lane & 3;
    int col = warp / 6, warpIn = warp % 6;
    int lineBase = base + col;
    int r0 = warpIn * 16 + g, r1 = r0 + 8;

    uint qh0 = s_qh[col][r0], qh1 = s_qh[col][r1];
    uint qx0 = __byte_perm(qh0, qh0, 0x1010), qy0 = __byte_perm(qh0, qh0, 0x3232);
    uint qx1 = __byte_perm(qh1, qh1, 0x1010), qy1 = __byte_perm(qh1, qh1, 0x3232);

    float D0[4] = {0, 0, 0, 0};
    float D1[4] = {0, 0, 0, 0};
    float S[4]  = {0, 0, 0, 0};

#pragma unroll
    for (int kt = 0; kt < 6; kt++) {
        int pi = kt * 8 + tig;
        ull kA = *(const ull*)&s_kp[col][pi * 2];
        ull kB = *(const ull*)&s_kp[col][(pi + 4) * 2];
        uint kxA = (uint)kA, kyA = (uint)(kA >> 32);
        uint kxB = (uint)kB, kyB = (uint)(kB >> 32);

        uint a0 = ex2h2(hfma2(qx0, kxA, hmul2(qy0, kyA)));
        uint a1 = ex2h2(hfma2(qx1, kxA, hmul2(qy1, kyA)));
        uint a2 = ex2h2(hfma2(qx0, kxB, hmul2(qy0, kyB)));
        uint a3 = ex2h2(hfma2(qx1, kxB, hmul2(qy1, kyB)));

        int j0 = 2 * pi, j1 = 2 * (pi + 4);
        if (r0 == j0)     a0 &= 0xFFFF0000u;
        if (r0 == j0 + 1) a0 &= 0x0000FFFFu;
        if (r1 == j0)     a1 &= 0xFFFF0000u;
        if (r1 == j0 + 1) a1 &= 0x0000FFFFu;
        if (r0 == j1)     a2 &= 0xFFFF0000u;
        if (r0 == j1 + 1) a2 &= 0x0000FFFFu;
        if (r1 == j1)     a3 &= 0xFFFF0000u;
        if (r1 == j1 + 1) a3 &= 0x0000FFFFu;

        ull b0 = *(const ull*)&sVh[col][pi * SVS + 2 * g];
        ull b1 = *(const ull*)&sVh[col][(pi + 4) * SVS + 2 * g];
        uint b0lo = (uint)b0, b0hi = (uint)(b0 >> 32);
        uint b1lo = (uint)b1, b1hi = (uint)(b1 >> 32);

        mmah16(D0[0], D0[1], D0[2], D0[3], a0, a1, a2, a3, b0lo, b1lo);
        mmah16(D1[0], D1[1], D1[2], D1[3], a0, a1, a2, a3, b0hi, b1hi);
        mmah16(S[0],  S[1],  S[2],  S[3],  a0, a1, a2, a3, H2_ONES, H2_ONES);
    }

    int p0 = lineBase + r0 * Wn, p1 = lineBase + r1 * Wn;
    if (tig == 0) { g_sH[p0] = S[0]; g_sH[p1] = S[2]; }
    g_oh[(size_t)p0 * 8 + tig]     = h2pack(D0[0], D0[1]);
    g_oh[(size_t)p1 * 8 + tig]     = h2pack(D0[2], D0[3]);
    g_oh[(size_t)p0 * 8 + 4 + tig] = h2pack(D1[0], D1[1]);
    g_oh[(size_t)p1 * 8 + 4 + tig] = h2pack(D1[2], D1[3]);
}

// ---------------------------------------------------------------------------
// Pass B: one row line per block, 12 warps. Combine + residual.
// iter1 (dst==null): residual from fp32 xin, write fp16 g_yres (uint stores).
// iter2 (dst!=null): residual from g_yres, write fp32 dst.
// ---------------------------------------------------------------------------
__global__ __launch_bounds__(384) void passB_kernel(const float* __restrict__ xin,
                                                    float* __restrict__ dst,
                                                    const float* __restrict__ gammap)
{
    __shared__ __align__(8) uint s_qh[192];
    __shared__ __align__(8) uint s_kp[192];
    __shared__ __align__(8) uint sVh[96 * SVS];

    int d = blockIdx.y, h = blockIdx.x, t = threadIdx.x;
    int lineBase = d * HWn + h * Wn;

    if (t < 192) {
        int p = lineBase + t;
        s_qh[t] = g_qh[p];
        uint kh = g_kh[p];
        __half* kp = (__half*)s_kp;
        int rp = t >> 1, b = t & 1;
        kp[rp * 4 + b]     = ((__half2*)&kh)->x;
        kp[rp * 4 + 2 + b] = ((__half2*)&kh)->y;
    } else {
        int t2 = t - 192;                 // 0..191
        int rp = t2 >> 1, hs = t2 & 1;
        int pe = lineBase + 2 * rp;
        uint4 e = *(const uint4*)&g_vh[(size_t)pe * 8 + hs * 4];
        uint4 o = *(const uint4*)&g_vh[(size_t)(pe + 1) * 8 + hs * 4];
        stageV(&sVh[rp * SVS], e, o, hs);
    }

    int warp = t >> 5, lane = t & 31, g = lane >> 2, tig = lane & 3;
    int r0 = warp * 16 + g, r1 = r0 + 8;
    int p0 = lineBase + r0, p1 = lineBase + r1;

    // prefetch epilogue operands (overlap latency with mainloop)
    float sH0 = g_sH[p0], sH1 = g_sH[p1];
    uint oh00 = g_oh[(size_t)p0 * 8 + tig];
    uint oh01 = g_oh[(size_t)p0 * 8 + 4 + tig];
    uint oh10 = g_oh[(size_t)p1 * 8 + tig];
    uint oh11 = g_oh[(size_t)p1 * 8 + 4 + tig];
    uint xr00 = 0, xr01 = 0, xr10 = 0, xr11 = 0;
    if (!xin) {   // iter2: residual from fp16 intermediate
        xr00 = g_yres[(size_t)p0 * 8 + tig];
        xr01 = g_yres[(size_t)p0 * 8 + 4 + tig];
        xr10 = g_yres[(size_t)p1 * 8 + tig];
        xr11 = g_yres[(size_t)p1 * 8 + 4 + tig];
    }
    float gamma = gammap[0];

    __syncthreads();

    uint qh0 = s_qh[r0], qh1 = s_qh[r1];
    uint qx0 = __byte_perm(qh0, qh0, 0x1010), qy0 = __byte_perm(qh0, qh0, 0x3232);
    uint qx1 = __byte_perm(qh1, qh1, 0x1010), qy1 = __byte_perm(qh1, qh1, 0x3232);

    float D0[4] = {0, 0, 0, 0};
    float D1[4] = {0, 0, 0, 0};
    float S[4]  = {0, 0, 0, 0};

#pragma unroll
    for (int kt = 0; kt < 12; kt++) {
        int pi = kt * 8 + tig;
        ull kA = *(const ull*)&s_kp[pi * 2];
        ull kB = *(const ull*)&s_kp[(pi + 4) * 2];
        uint kxA = (uint)kA, kyA = (uint)(kA >> 32);
        uint kxB = (uint)kB, kyB = (uint)(kB >> 32);

        uint a0 = ex2h2(hfma2(qx0, kxA, hmul2(qy0, kyA)));
        uint a1 = ex2h2(hfma2(qx1, kxA, hmul2(qy1, kyA)));
        uint a2 = ex2h2(hfma2(qx0, kxB, hmul2(qy0, kyB)));
        uint a3 = ex2h2(hfma2(qx1, kxB, hmul2(qy1, kyB)));

        ull b0 = *(const ull*)&sVh[pi * SVS + 2 * g];
        ull b1 = *(const ull*)&sVh[(pi + 4) * SVS + 2 * g];
        uint b0lo = (uint)b0, b0hi = (uint)(b0 >> 32);
        uint b1lo = (uint)b1, b1hi = (uint)(b1 >> 32);

        mmah16(D0[0], D0[1], D0[2], D0[3], a0, a1, a2, a3, b0lo, b1lo);
        mmah16(D1[0], D1[1], D1[2], D1[3], a0, a1, a2, a3, b0hi, b1hi);
        mmah16(S[0],  S[1],  S[2],  S[3],  a0, a1, a2, a3, H2_ONES, H2_ONES);
    }

    float inv0 = __fdividef(gamma, S[0] + sH0);
    float inv1 = __fdividef(gamma, S[2] + sH1);

    float2 ohA0 = h2unpack(oh00), ohA1 = h2unpack(oh10);
    float2 ohB0 = h2unpack(oh01), ohB1 = h2unpack(oh11);

    // attention outputs for (p0, ch 2tig/2tig+1), (p1, ...), and +8 channels
    float aA0x = (D0[0] + ohA0.x) * inv0, aA0y = (D0[1] + ohA0.y) * inv0;
    float aA1x = (D0[2] + ohA1.x) * inv1, aA1y = (D0[3] + ohA1.y) * inv1;
    float aB0x = (D1[0] + ohB0.x) * inv0, aB0y = (D1[1] + ohB0.y) * inv0;
    float aB1x = (D1[2] + ohB1.x) * inv1, aB1y = (D1[3] + ohB1.y) * inv1;

    if (dst) {   // iter2: fp32 channel-major output, residual from g_yres
        float2 x00 = h2unpack(xr00), x01 = h2unpack(xr01);
        float2 x10 = h2unpack(xr10), x11 = h2unpack(xr11);
        int c = 2 * tig;
        dst[c * Pn + p0]       = x00.x + aA0x;
        dst[(c + 1) * Pn + p0] = x00.y + aA0y;
        dst[c * Pn + p1]       = x10.x + aA1x;
        dst[(c + 1) * Pn + p1] = x10.y + aA1y;
        int c2 = 8 + 2 * tig;
        dst[c2 * Pn + p0]       = x01.x + aB0x;
        dst[(c2 + 1) * Pn + p0] = x01.y + aB0y;
        dst[c2 * Pn + p1]       = x11.x + aB1x;
        dst[(c2 + 1) * Pn + p1] = x11.y + aB1y;
    } else {     // iter1: residual from fp32 x, write fp16 pixel-major g_yres
        int c = 2 * tig, c2 = 8 + 2 * tig;
        float xA0x = xin[c * Pn + p0],        xA0y = xin[(c + 1) * Pn + p0];
        float xA1x = xin[c * Pn + p1],        xA1y = xin[(c + 1) * Pn + p1];
        float xB0x = xin[c2 * Pn + p0],       xB0y = xin[(c2 + 1) * Pn + p0];
        float xB1x = xin[c2 * Pn + p1],       xB1y = xin[(c2 + 1) * Pn + p1];
        g_yres[(size_t)p0 * 8 + tig]     = h2pack(xA0x + aA0x, xA0y + aA0y);
        g_yres[(size_t)p1 * 8 + tig]     = h2pack(xA1x + aA1x, xA1y + aA1y);
        g_yres[(size_t)p0 * 8 + 4 + tig] = h2pack(xB0x + aB0x, xB0y + aB0y);
        g_yres[(size_t)p1 * 8 + 4 + tig] = h2pack(xB1x + aB1x, xB1y + aB1y);
    }
}

// ---------------------------------------------------------------------------
extern "C" void kernel_launch(void* const* d_in, const int* in_sizes, int n_in,
                              void* d_out, int out_size)
{
    const float* x     = (const float*)d_in[0];
    const float* qw    = (const float*)d_in[1];
    const float* qb    = (const float*)d_in[2];
    const float* kw    = (const float*)d_in[3];
    const float* kb    = (const float*)d_in[4];
    const float* vw    = (const float*)d_in[5];
    const float* vb    = (const float*)d_in[6];
    const float* gamma = (const float*)d_in[7];
    float* out = (float*)d_out;

    dim3 gA(Wn / 4, Dn);   // 48 x 24 blocks, 768 threads
    dim3 gB(Hn, Dn);       // 96 x 24 blocks, 384 threads
    int qkvBlocks = Pn / 256;   // 1728

    qkv_kernel<<<qkvBlocks, 128>>>(x, qw, qb, kw, kb, vw, vb);
    passA_kernel<<<gA, 768>>>();
    passB_kernel<<<gB, 384>>>(x, nullptr, gamma);       // writes g_yres (fp16)

    qkv_kernel<<<qkvBlocks, 128>>>(nullptr, qw, qb, kw, kb, vw, vb);  // reads g_yres
    passA_kernel<<<gA, 768>>>();
    passB_kernel<<<gB, 384>>>(nullptr, out, gamma);     // residual from g_yres
}